// round 1
// baseline (speedup 1.0000x reference)
#include <cuda_runtime.h>

#define NB 2
#define NS 2048
#define NE 1024
#define NH 16
#define ND 64
#define NM (NB*NS)      // 4096 rows
#define NHD (NH*ND)     // 1024

#define LDP 68          // padded row stride for attention smem tiles (16B-aligned, bank-skewed)

// Scratch (allocation-free rule: __device__ globals)
__device__ float g_xn[NM*NE];
__device__ float g_q[NM*NHD];
__device__ float g_k[NM*NHD];
__device__ float g_v[NM*NHD];
__device__ float g_attn[NM*NHD];

// ---------------------------------------------------------------------------
// LayerNorm: one block per row, 256 threads, float4 per thread (E=1024)
// ---------------------------------------------------------------------------
__global__ void __launch_bounds__(256) ln_kernel(const float* __restrict__ x,
                                                 const float* __restrict__ gam,
                                                 const float* __restrict__ bet) {
    int row = blockIdx.x;
    int t = threadIdx.x;
    const float4* xr = (const float4*)(x + (size_t)row * NE);
    float4 xv = xr[t];
    float s  = xv.x + xv.y + xv.z + xv.w;
    float ss = xv.x*xv.x + xv.y*xv.y + xv.z*xv.z + xv.w*xv.w;
    #pragma unroll
    for (int m = 16; m; m >>= 1) {
        s  += __shfl_xor_sync(0xffffffffu, s,  m);
        ss += __shfl_xor_sync(0xffffffffu, ss, m);
    }
    __shared__ float sh1[8], sh2[8];
    if ((t & 31) == 0) { sh1[t >> 5] = s; sh2[t >> 5] = ss; }
    __syncthreads();
    s = 0.f; ss = 0.f;
    #pragma unroll
    for (int w = 0; w < 8; w++) { s += sh1[w]; ss += sh2[w]; }
    float mean = s * (1.f / NE);
    float var  = ss * (1.f / NE) - mean * mean;
    float rstd = rsqrtf(var + 1e-5f);
    float4 gv = ((const float4*)gam)[t];
    float4 bv = ((const float4*)bet)[t];
    float4 o;
    o.x = (xv.x - mean) * rstd * gv.x + bv.x;
    o.y = (xv.y - mean) * rstd * gv.y + bv.y;
    o.z = (xv.z - mean) * rstd * gv.z + bv.z;
    o.w = (xv.w - mean) * rstd * gv.w + bv.w;
    ((float4*)(g_xn + (size_t)row * NE))[t] = o;
}

// ---------------------------------------------------------------------------
// SGEMM: C[M,N] = A[M,K] @ W[K,N] + bias (+ resid). 128x128 tile, BK=16,
// 256 threads, 8x8 per thread, float4 everywhere. M,N,K multiples of 128/16.
// ---------------------------------------------------------------------------
template<bool RESID>
__global__ void __launch_bounds__(256) sgemm128(
    const float* __restrict__ A, const float* __restrict__ W,
    const float* __restrict__ bias, const float* __restrict__ resid,
    float* __restrict__ C, int M, int N, int K)
{
    __shared__ float As[16][128];
    __shared__ float Bs[16][128];
    int tid = threadIdx.x;
    int bm = blockIdx.y, bn = blockIdx.x;
    int tm = tid >> 4, tn = tid & 15;
    const float* Ab = A + (size_t)bm * 128 * K;
    const float* Wb = W + bn * 128;
    float acc[8][8] = {};

    for (int k0 = 0; k0 < K; k0 += 16) {
        #pragma unroll
        for (int l = 0; l < 2; l++) {
            int idx = tid + l * 256;
            int r = idx >> 2, c4 = (idx & 3) * 4;
            float4 av = *(const float4*)(Ab + (size_t)r * K + k0 + c4);
            As[c4 + 0][r] = av.x;
            As[c4 + 1][r] = av.y;
            As[c4 + 2][r] = av.z;
            As[c4 + 3][r] = av.w;
            int br = idx >> 5, bc = (idx & 31) * 4;
            *(float4*)&Bs[br][bc] = *(const float4*)(Wb + (size_t)(k0 + br) * N + bc);
        }
        __syncthreads();
        #pragma unroll
        for (int kk = 0; kk < 16; kk++) {
            float ra[8], rb[8];
            *(float4*)&ra[0] = *(const float4*)&As[kk][tm * 8];
            *(float4*)&ra[4] = *(const float4*)&As[kk][tm * 8 + 4];
            *(float4*)&rb[0] = *(const float4*)&Bs[kk][tn * 8];
            *(float4*)&rb[4] = *(const float4*)&Bs[kk][tn * 8 + 4];
            #pragma unroll
            for (int i = 0; i < 8; i++)
                #pragma unroll
                for (int j = 0; j < 8; j++)
                    acc[i][j] = fmaf(ra[i], rb[j], acc[i][j]);
        }
        __syncthreads();
    }

    int col0 = bn * 128 + tn * 8;
    float bias0[8];
    *(float4*)&bias0[0] = *(const float4*)(bias + col0);
    *(float4*)&bias0[4] = *(const float4*)(bias + col0 + 4);
    #pragma unroll
    for (int i = 0; i < 8; i++) {
        int row = bm * 128 + tm * 8 + i;
        float* cp = C + (size_t)row * N + col0;
        float v0[8];
        #pragma unroll
        for (int j = 0; j < 8; j++) v0[j] = acc[i][j] + bias0[j];
        if (RESID) {
            const float* rp = resid + (size_t)row * N + col0;
            float4 r0 = *(const float4*)rp;
            float4 r1 = *(const float4*)(rp + 4);
            v0[0] += r0.x; v0[1] += r0.y; v0[2] += r0.z; v0[3] += r0.w;
            v0[4] += r1.x; v0[5] += r1.y; v0[6] += r1.z; v0[7] += r1.w;
        }
        *(float4*)cp       = make_float4(v0[0], v0[1], v0[2], v0[3]);
        *(float4*)(cp + 4) = make_float4(v0[4], v0[5], v0[6], v0[7]);
    }
}

// ---------------------------------------------------------------------------
// Causal flash attention: one block per (q-tile of 64, head, batch).
// 256 threads = 16x16 grid, 4x4 register micro-tile. Online softmax.
// Skips fully-masked key tiles (kt > qt).
// ---------------------------------------------------------------------------
__global__ void __launch_bounds__(256) attn_kernel() {
    extern __shared__ float sm[];
    float* Qs  = sm;               // [64][LDP] (pre-scaled by 1/sqrt(D))
    float* KsT = Qs + 64 * LDP;    // [d=64][c=64] transposed K tile
    float* Vs  = KsT + 64 * LDP;   // [c=64][d=64]
    float* Ps  = Vs + 64 * LDP;    // [r=64][c=64] probabilities

    int qt = blockIdx.x, h = blockIdx.y, b = blockIdx.z;
    int tid = threadIdx.x;
    int tm = tid >> 4, tn = tid & 15;
    const float scale = 0.125f; // 1/sqrt(64)

    // Load + pre-scale Q tile
    #pragma unroll
    for (int l = 0; l < 4; l++) {
        int idx = tid + l * 256;
        int r = idx >> 4, c = (idx & 15) * 4;
        const float* gp = g_q + (size_t)(b * NS + qt * 64 + r) * NHD + h * ND + c;
        float4 qv = *(const float4*)gp;
        float* qs = Qs + r * LDP + c;
        qs[0] = qv.x * scale; qs[1] = qv.y * scale;
        qs[2] = qv.z * scale; qs[3] = qv.w * scale;
    }

    float m_i[4], l_i[4], o[4][4];
    #pragma unroll
    for (int i = 0; i < 4; i++) {
        m_i[i] = -3e38f; l_i[i] = 0.f;
        #pragma unroll
        for (int j = 0; j < 4; j++) o[i][j] = 0.f;
    }

    for (int kt = 0; kt <= qt; kt++) {
        __syncthreads();  // Qs ready (iter 0); prior iter's Ps/Vs reads done
        #pragma unroll
        for (int l = 0; l < 4; l++) {
            int idx = tid + l * 256;
            int r = idx >> 4, c = (idx & 15) * 4;
            size_t g0 = (size_t)(b * NS + kt * 64 + r) * NHD + h * ND + c;
            float4 kv = *(const float4*)(g_k + g0);
            KsT[(c + 0) * LDP + r] = kv.x;
            KsT[(c + 1) * LDP + r] = kv.y;
            KsT[(c + 2) * LDP + r] = kv.z;
            KsT[(c + 3) * LDP + r] = kv.w;
            *(float4*)&Vs[r * LDP + c] = *(const float4*)(g_v + g0);
        }
        __syncthreads();

        // S = Q K^T (scaled)
        float s4[4][4] = {};
        #pragma unroll 16
        for (int d = 0; d < 64; d++) {
            float4 kb = *(const float4*)&KsT[d * LDP + tn * 4];
            #pragma unroll
            for (int i = 0; i < 4; i++) {
                float qa = Qs[(tm * 4 + i) * LDP + d];
                s4[i][0] = fmaf(qa, kb.x, s4[i][0]);
                s4[i][1] = fmaf(qa, kb.y, s4[i][1]);
                s4[i][2] = fmaf(qa, kb.z, s4[i][2]);
                s4[i][3] = fmaf(qa, kb.w, s4[i][3]);
            }
        }

        if (kt == qt) { // diagonal tile: causal mask within tile
            #pragma unroll
            for (int i = 0; i < 4; i++)
                #pragma unroll
                for (int j = 0; j < 4; j++)
                    if (tn * 4 + j > tm * 4 + i) s4[i][j] = -3e38f;
        }

        // Online softmax update (row stats shared across the 16 tn-lanes)
        #pragma unroll
        for (int i = 0; i < 4; i++) {
            float mx = fmaxf(fmaxf(s4[i][0], s4[i][1]), fmaxf(s4[i][2], s4[i][3]));
            #pragma unroll
            for (int m2 = 8; m2; m2 >>= 1)
                mx = fmaxf(mx, __shfl_xor_sync(0xffffffffu, mx, m2));
            float mnew = fmaxf(m_i[i], mx);
            float alpha = __expf(m_i[i] - mnew);
            m_i[i] = mnew;
            float ps = 0.f;
            #pragma unroll
            for (int j = 0; j < 4; j++) {
                float p = __expf(s4[i][j] - mnew);
                s4[i][j] = p;
                ps += p;
            }
            #pragma unroll
            for (int m2 = 8; m2; m2 >>= 1)
                ps += __shfl_xor_sync(0xffffffffu, ps, m2);
            l_i[i] = l_i[i] * alpha + ps;
            #pragma unroll
            for (int j = 0; j < 4; j++) o[i][j] *= alpha;
            *(float4*)&Ps[(tm * 4 + i) * LDP + tn * 4] =
                make_float4(s4[i][0], s4[i][1], s4[i][2], s4[i][3]);
        }
        __syncthreads();

        // O += P V
        #pragma unroll 16
        for (int c = 0; c < 64; c++) {
            float4 vb = *(const float4*)&Vs[c * LDP + tn * 4];
            #pragma unroll
            for (int i = 0; i < 4; i++) {
                float p = Ps[(tm * 4 + i) * LDP + c];
                o[i][0] = fmaf(p, vb.x, o[i][0]);
                o[i][1] = fmaf(p, vb.y, o[i][1]);
                o[i][2] = fmaf(p, vb.z, o[i][2]);
                o[i][3] = fmaf(p, vb.w, o[i][3]);
            }
        }
    }

    // Normalize + write back
    #pragma unroll
    for (int i = 0; i < 4; i++) {
        float inv = 1.f / l_i[i];
        int row = b * NS + qt * 64 + tm * 4 + i;
        float* op = g_attn + (size_t)row * NHD + h * ND + tn * 4;
        *(float4*)op = make_float4(o[i][0] * inv, o[i][1] * inv,
                                   o[i][2] * inv, o[i][3] * inv);
    }
}

// ---------------------------------------------------------------------------
// Launch
// ---------------------------------------------------------------------------
extern "C" void kernel_launch(void* const* d_in, const int* in_sizes, int n_in,
                              void* d_out, int out_size) {
    const float* x    = (const float*)d_in[0];
    const float* ln_g = (const float*)d_in[1];
    const float* ln_b = (const float*)d_in[2];
    const float* wq   = (const float*)d_in[3];
    const float* bq   = (const float*)d_in[4];
    const float* wk   = (const float*)d_in[5];
    const float* bk   = (const float*)d_in[6];
    const float* wv   = (const float*)d_in[7];
    const float* bv   = (const float*)d_in[8];
    const float* wo   = (const float*)d_in[9];
    const float* bo   = (const float*)d_in[10];
    float* out = (float*)d_out;

    float *xn, *q, *k, *v, *attn;
    cudaGetSymbolAddress((void**)&xn,   g_xn);
    cudaGetSymbolAddress((void**)&q,    g_q);
    cudaGetSymbolAddress((void**)&k,    g_k);
    cudaGetSymbolAddress((void**)&v,    g_v);
    cudaGetSymbolAddress((void**)&attn, g_attn);

    ln_kernel<<<NM, 256>>>(x, ln_g, ln_b);

    dim3 gqkv(NHD / 128, NM / 128);
    sgemm128<false><<<gqkv, 256>>>(xn, wq, bq, nullptr, q, NM, NHD, NE);
    sgemm128<false><<<gqkv, 256>>>(xn, wk, bk, nullptr, k, NM, NHD, NE);
    sgemm128<false><<<gqkv, 256>>>(xn, wv, bv, nullptr, v, NM, NHD, NE);

    size_t shmem = (size_t)4 * 64 * LDP * sizeof(float); // 69632 B
    cudaFuncSetAttribute(attn_kernel,
                         cudaFuncAttributeMaxDynamicSharedMemorySize, (int)shmem);
    attn_kernel<<<dim3(NS / 64, NH, NB), 256, shmem>>>();

    sgemm128<true><<<dim3(NE / 128, NM / 128), 256>>>(attn, wo, bo, x, out,
                                                      NM, NE, NHD);
}

// round 2
// speedup vs baseline: 1.5735x; 1.5735x over previous
#include <cuda_runtime.h>
#include <cuda_bf16.h>

#define NB 2
#define NS 2048
#define NE 1024
#define NH 16
#define ND 64
#define NM (NB*NS)      // 4096 rows
#define NHD (NH*ND)     // 1024

#define LDP 68          // padded row stride for attention smem tiles

// ---------------------------------------------------------------------------
// Scratch (__device__ globals; allocation-free rule)
// ---------------------------------------------------------------------------
__device__ __align__(16) __nv_bfloat16 g_xnh[NM*NE];
__device__ __align__(16) __nv_bfloat16 g_xnl[NM*NE];
__device__ __align__(16) float g_q[NM*NHD];
__device__ __align__(16) float g_k[NM*NHD];
__device__ __align__(16) float g_v[NM*NHD];
__device__ __align__(16) __nv_bfloat16 g_aoh[NM*NHD];
__device__ __align__(16) __nv_bfloat16 g_aol[NM*NHD];
__device__ __align__(16) __nv_bfloat16 g_wh[4][NE*NHD];
__device__ __align__(16) __nv_bfloat16 g_wl[4][NE*NHD];

// ---------------------------------------------------------------------------
// PTX helpers
// ---------------------------------------------------------------------------
__device__ __forceinline__ void ldsm4(unsigned r[4], unsigned addr) {
    asm volatile("ldmatrix.sync.aligned.m8n8.x4.shared.b16 {%0,%1,%2,%3}, [%4];"
                 : "=r"(r[0]), "=r"(r[1]), "=r"(r[2]), "=r"(r[3]) : "r"(addr));
}
__device__ __forceinline__ void ldsm4t(unsigned r[4], unsigned addr) {
    asm volatile("ldmatrix.sync.aligned.m8n8.x4.trans.shared.b16 {%0,%1,%2,%3}, [%4];"
                 : "=r"(r[0]), "=r"(r[1]), "=r"(r[2]), "=r"(r[3]) : "r"(addr));
}
__device__ __forceinline__ void mma16816(float d[4], const unsigned a[4],
                                         unsigned b0, unsigned b1) {
    asm volatile("mma.sync.aligned.m16n8k16.row.col.f32.bf16.bf16.f32 "
                 "{%0,%1,%2,%3}, {%4,%5,%6,%7}, {%8,%9}, {%0,%1,%2,%3};"
                 : "+f"(d[0]), "+f"(d[1]), "+f"(d[2]), "+f"(d[3])
                 : "r"(a[0]), "r"(a[1]), "r"(a[2]), "r"(a[3]), "r"(b0), "r"(b1));
}
__device__ __forceinline__ void cpa16(unsigned saddr, const void* g) {
    asm volatile("cp.async.cg.shared.global [%0], [%1], 16;" :: "r"(saddr), "l"(g));
}
__device__ __forceinline__ void cpa_commit() {
    asm volatile("cp.async.commit_group;");
}

// ---------------------------------------------------------------------------
// LayerNorm: one block per row; writes bf16 hi/lo split
// ---------------------------------------------------------------------------
__global__ void __launch_bounds__(256) ln_kernel(const float* __restrict__ x,
                                                 const float* __restrict__ gam,
                                                 const float* __restrict__ bet) {
    int row = blockIdx.x;
    int t = threadIdx.x;
    const float4* xr = (const float4*)(x + (size_t)row * NE);
    float4 xv = xr[t];
    float s  = xv.x + xv.y + xv.z + xv.w;
    float ss = xv.x*xv.x + xv.y*xv.y + xv.z*xv.z + xv.w*xv.w;
    #pragma unroll
    for (int m = 16; m; m >>= 1) {
        s  += __shfl_xor_sync(0xffffffffu, s,  m);
        ss += __shfl_xor_sync(0xffffffffu, ss, m);
    }
    __shared__ float sh1[8], sh2[8];
    if ((t & 31) == 0) { sh1[t >> 5] = s; sh2[t >> 5] = ss; }
    __syncthreads();
    s = 0.f; ss = 0.f;
    #pragma unroll
    for (int w = 0; w < 8; w++) { s += sh1[w]; ss += sh2[w]; }
    float mean = s * (1.f / NE);
    float var  = ss * (1.f / NE) - mean * mean;
    float rstd = rsqrtf(var + 1e-5f);
    float4 gv = ((const float4*)gam)[t];
    float4 bv = ((const float4*)bet)[t];
    float o[4];
    o[0] = (xv.x - mean) * rstd * gv.x + bv.x;
    o[1] = (xv.y - mean) * rstd * gv.y + bv.y;
    o[2] = (xv.z - mean) * rstd * gv.z + bv.z;
    o[3] = (xv.w - mean) * rstd * gv.w + bv.w;
    size_t base = (size_t)row * NE + t * 4;
    #pragma unroll
    for (int j = 0; j < 4; j++) {
        __nv_bfloat16 h = __float2bfloat16_rn(o[j]);
        g_xnh[base + j] = h;
        g_xnl[base + j] = __float2bfloat16_rn(o[j] - __bfloat162float(h));
    }
}

// ---------------------------------------------------------------------------
// Weight split: fp32 -> bf16 hi/lo
// ---------------------------------------------------------------------------
__global__ void __launch_bounds__(256) splitw_kernel(const float* __restrict__ src,
                                                     __nv_bfloat16* __restrict__ dh,
                                                     __nv_bfloat16* __restrict__ dl) {
    int idx = (blockIdx.x * 256 + threadIdx.x) * 4;
    float4 v = *(const float4*)(src + idx);
    float a[4] = {v.x, v.y, v.z, v.w};
    #pragma unroll
    for (int j = 0; j < 4; j++) {
        __nv_bfloat16 h = __float2bfloat16_rn(a[j]);
        dh[idx + j] = h;
        dl[idx + j] = __float2bfloat16_rn(a[j] - __bfloat162float(h));
    }
}

// ---------------------------------------------------------------------------
// bf16x3 tensor-core GEMM: C[M,N] = (Ah+Al)@(Bh+Bl) + bias (+resid)
// 128x128 block tile, BK=32, 8 warps (2x4), 64x32 warp tile,
// cp.async double buffer, XOR-swizzled smem, ldmatrix fragments.
// Smem per buffer: A 16KB (128 rows x 128B: chunks 0-3 hi, 4-7 lo),
//                  Bh 8KB, Bl 8KB. Two buffers = 64KB dynamic.
// ---------------------------------------------------------------------------
template<bool RESID>
__global__ void __launch_bounds__(256) gemm_bf16x3(
    const __nv_bfloat16* __restrict__ Ah, const __nv_bfloat16* __restrict__ Al,
    const __nv_bfloat16* __restrict__ Bh, const __nv_bfloat16* __restrict__ Bl,
    const float* __restrict__ bias, const float* __restrict__ resid,
    float* __restrict__ C, int M, int N, int K)
{
    extern __shared__ char smraw[];
    unsigned sbase = (unsigned)__cvta_generic_to_shared(smraw);
    int tid = threadIdx.x;
    int bm = blockIdx.y, bn = blockIdx.x;
    int lane = tid & 31, wid = tid >> 5;
    int wm = wid >> 2, wn = wid & 3;

    float acc[4][4][4];
    #pragma unroll
    for (int i = 0; i < 4; i++)
        #pragma unroll
        for (int j = 0; j < 4; j++)
            #pragma unroll
            for (int c = 0; c < 4; c++) acc[i][j][c] = 0.f;

    const int iters = K >> 5;

    // --- cp.async tile issue ---
    auto issue = [&](int buf, int k0) {
        unsigned ab  = sbase + buf * 32768;
        unsigned bbh = ab + 16384;
        unsigned bbl = ab + 24576;
        #pragma unroll
        for (int i = 0; i < 2; i++) {
            int u = tid + i * 256;          // A: 512 16B-units
            int row = u >> 2, c = u & 3;    // c: hi chunk (k = 8c..8c+7)
            const __nv_bfloat16* ga = Ah + (size_t)(bm * 128 + row) * K + k0 + c * 8;
            const __nv_bfloat16* gl = Al + (size_t)(bm * 128 + row) * K + k0 + c * 8;
            cpa16(ab + row * 128 + ((c ^ (row & 7)) << 4), ga);
            cpa16(ab + row * 128 + (((c + 4) ^ (row & 7)) << 4), gl);
        }
        #pragma unroll
        for (int i = 0; i < 2; i++) {
            int u = tid + i * 256;          // B: 512 16B-units
            int k = u >> 4, c = u & 15;     // c: 8-col chunk
            size_t goff = (size_t)(k0 + k) * N + bn * 128 + c * 8;
            unsigned soff = k * 256 + ((c ^ (k & 7)) << 4);
            cpa16(bbh + soff, Bh + goff);
            cpa16(bbl + soff, Bl + goff);
        }
        cpa_commit();
    };

    issue(0, 0);

    int r = lane & 7, sel = lane >> 3;
    for (int it = 0; it < iters; it++) {
        if (it + 1 < iters) {
            issue((it + 1) & 1, (it + 1) << 5);
            asm volatile("cp.async.wait_group 1;");
        } else {
            asm volatile("cp.async.wait_group 0;");
        }
        __syncthreads();

        unsigned ab  = sbase + (it & 1) * 32768;
        unsigned bbh = ab + 16384;
        unsigned bbl = ab + 24576;
        #pragma unroll
        for (int s = 0; s < 2; s++) {
            unsigned aH[4][4], aL[4][4], bHf[2][4], bLf[2][4];
            #pragma unroll
            for (int mf = 0; mf < 4; mf++) {
                int row = wm * 64 + mf * 16 + r + ((sel & 1) << 3);
                int ch = 2 * s + (sel >> 1);
                ldsm4(aH[mf], ab + row * 128 + ((ch ^ (row & 7)) << 4));
                ldsm4(aL[mf], ab + row * 128 + (((ch + 4) ^ (row & 7)) << 4));
            }
            #pragma unroll
            for (int np = 0; np < 2; np++) {
                int k = 16 * s + r + ((sel & 1) << 3);
                int ch = wn * 4 + np * 2 + (sel >> 1);
                unsigned off = k * 256 + ((ch ^ (k & 7)) << 4);
                ldsm4t(bHf[np], bbh + off);
                ldsm4t(bLf[np], bbl + off);
            }
            #pragma unroll
            for (int mf = 0; mf < 4; mf++)
                #pragma unroll
                for (int nf = 0; nf < 4; nf++) {
                    unsigned bh0 = bHf[nf >> 1][(nf & 1) * 2];
                    unsigned bh1 = bHf[nf >> 1][(nf & 1) * 2 + 1];
                    unsigned bl0 = bLf[nf >> 1][(nf & 1) * 2];
                    unsigned bl1 = bLf[nf >> 1][(nf & 1) * 2 + 1];
                    mma16816(acc[mf][nf], aH[mf], bh0, bh1);
                    mma16816(acc[mf][nf], aH[mf], bl0, bl1);
                    mma16816(acc[mf][nf], aL[mf], bh0, bh1);
                }
        }
        __syncthreads();
    }

    // --- epilogue ---
    int g = lane >> 2, t2 = (lane & 3) * 2;
    #pragma unroll
    for (int mf = 0; mf < 4; mf++) {
        int row0 = bm * 128 + wm * 64 + mf * 16 + g;
        #pragma unroll
        for (int nf = 0; nf < 4; nf++) {
            int col = bn * 128 + wn * 32 + nf * 8 + t2;
            float b0 = bias[col], b1 = bias[col + 1];
            float v00 = acc[mf][nf][0] + b0, v01 = acc[mf][nf][1] + b1;
            float v10 = acc[mf][nf][2] + b0, v11 = acc[mf][nf][3] + b1;
            if (RESID) {
                const float* rp0 = resid + (size_t)row0 * N + col;
                const float* rp1 = resid + (size_t)(row0 + 8) * N + col;
                v00 += rp0[0]; v01 += rp0[1];
                v10 += rp1[0]; v11 += rp1[1];
            }
            *(float2*)(C + (size_t)row0 * N + col)       = make_float2(v00, v01);
            *(float2*)(C + (size_t)(row0 + 8) * N + col) = make_float2(v10, v11);
        }
    }
}

// ---------------------------------------------------------------------------
// Causal flash attention (unchanged compute; bf16 hi/lo output)
// ---------------------------------------------------------------------------
__global__ void __launch_bounds__(256) attn_kernel() {
    extern __shared__ float sm[];
    float* Qs  = sm;
    float* KsT = Qs + 64 * LDP;
    float* Vs  = KsT + 64 * LDP;
    float* Ps  = Vs + 64 * LDP;

    int qt = blockIdx.x, h = blockIdx.y, b = blockIdx.z;
    int tid = threadIdx.x;
    int tm = tid >> 4, tn = tid & 15;
    const float scale = 0.125f;

    #pragma unroll
    for (int l = 0; l < 4; l++) {
        int idx = tid + l * 256;
        int rr = idx >> 4, c = (idx & 15) * 4;
        const float* gp = g_q + (size_t)(b * NS + qt * 64 + rr) * NHD + h * ND + c;
        float4 qv = *(const float4*)gp;
        float* qs = Qs + rr * LDP + c;
        qs[0] = qv.x * scale; qs[1] = qv.y * scale;
        qs[2] = qv.z * scale; qs[3] = qv.w * scale;
    }

    float m_i[4], l_i[4], o[4][4];
    #pragma unroll
    for (int i = 0; i < 4; i++) {
        m_i[i] = -3e38f; l_i[i] = 0.f;
        #pragma unroll
        for (int j = 0; j < 4; j++) o[i][j] = 0.f;
    }

    for (int kt = 0; kt <= qt; kt++) {
        __syncthreads();
        #pragma unroll
        for (int l = 0; l < 4; l++) {
            int idx = tid + l * 256;
            int rr = idx >> 4, c = (idx & 15) * 4;
            size_t g0 = (size_t)(b * NS + kt * 64 + rr) * NHD + h * ND + c;
            float4 kv = *(const float4*)(g_k + g0);
            KsT[(c + 0) * LDP + rr] = kv.x;
            KsT[(c + 1) * LDP + rr] = kv.y;
            KsT[(c + 2) * LDP + rr] = kv.z;
            KsT[(c + 3) * LDP + rr] = kv.w;
            *(float4*)&Vs[rr * LDP + c] = *(const float4*)(g_v + g0);
        }
        __syncthreads();

        float s4[4][4] = {};
        #pragma unroll 16
        for (int d = 0; d < 64; d++) {
            float4 kb = *(const float4*)&KsT[d * LDP + tn * 4];
            #pragma unroll
            for (int i = 0; i < 4; i++) {
                float qa = Qs[(tm * 4 + i) * LDP + d];
                s4[i][0] = fmaf(qa, kb.x, s4[i][0]);
                s4[i][1] = fmaf(qa, kb.y, s4[i][1]);
                s4[i][2] = fmaf(qa, kb.z, s4[i][2]);
                s4[i][3] = fmaf(qa, kb.w, s4[i][3]);
            }
        }

        if (kt == qt) {
            #pragma unroll
            for (int i = 0; i < 4; i++)
                #pragma unroll
                for (int j = 0; j < 4; j++)
                    if (tn * 4 + j > tm * 4 + i) s4[i][j] = -3e38f;
        }

        #pragma unroll
        for (int i = 0; i < 4; i++) {
            float mx = fmaxf(fmaxf(s4[i][0], s4[i][1]), fmaxf(s4[i][2], s4[i][3]));
            #pragma unroll
            for (int m2 = 8; m2; m2 >>= 1)
                mx = fmaxf(mx, __shfl_xor_sync(0xffffffffu, mx, m2));
            float mnew = fmaxf(m_i[i], mx);
            float alpha = __expf(m_i[i] - mnew);
            m_i[i] = mnew;
            float ps = 0.f;
            #pragma unroll
            for (int j = 0; j < 4; j++) {
                float p = __expf(s4[i][j] - mnew);
                s4[i][j] = p;
                ps += p;
            }
            #pragma unroll
            for (int m2 = 8; m2; m2 >>= 1)
                ps += __shfl_xor_sync(0xffffffffu, ps, m2);
            l_i[i] = l_i[i] * alpha + ps;
            #pragma unroll
            for (int j = 0; j < 4; j++) o[i][j] *= alpha;
            *(float4*)&Ps[(tm * 4 + i) * LDP + tn * 4] =
                make_float4(s4[i][0], s4[i][1], s4[i][2], s4[i][3]);
        }
        __syncthreads();

        #pragma unroll 16
        for (int c = 0; c < 64; c++) {
            float4 vb = *(const float4*)&Vs[c * LDP + tn * 4];
            #pragma unroll
            for (int i = 0; i < 4; i++) {
                float p = Ps[(tm * 4 + i) * LDP + c];
                o[i][0] = fmaf(p, vb.x, o[i][0]);
                o[i][1] = fmaf(p, vb.y, o[i][1]);
                o[i][2] = fmaf(p, vb.z, o[i][2]);
                o[i][3] = fmaf(p, vb.w, o[i][3]);
            }
        }
    }

    #pragma unroll
    for (int i = 0; i < 4; i++) {
        float inv = 1.f / l_i[i];
        int row = b * NS + qt * 64 + tm * 4 + i;
        size_t base = (size_t)row * NHD + h * ND + tn * 4;
        #pragma unroll
        for (int j = 0; j < 4; j++) {
            float v = o[i][j] * inv;
            __nv_bfloat16 hh = __float2bfloat16_rn(v);
            g_aoh[base + j] = hh;
            g_aol[base + j] = __float2bfloat16_rn(v - __bfloat162float(hh));
        }
    }
}

// ---------------------------------------------------------------------------
// Launch
// ---------------------------------------------------------------------------
extern "C" void kernel_launch(void* const* d_in, const int* in_sizes, int n_in,
                              void* d_out, int out_size) {
    const float* x    = (const float*)d_in[0];
    const float* ln_g = (const float*)d_in[1];
    const float* ln_b = (const float*)d_in[2];
    const float* wq   = (const float*)d_in[3];
    const float* bq   = (const float*)d_in[4];
    const float* wk   = (const float*)d_in[5];
    const float* bk   = (const float*)d_in[6];
    const float* wv   = (const float*)d_in[7];
    const float* bv   = (const float*)d_in[8];
    const float* wo   = (const float*)d_in[9];
    const float* bo   = (const float*)d_in[10];
    float* out = (float*)d_out;

    __nv_bfloat16 *xnh, *xnl, *aoh, *aol, *wh, *wl;
    float *q, *k, *v;
    cudaGetSymbolAddress((void**)&xnh, g_xnh);
    cudaGetSymbolAddress((void**)&xnl, g_xnl);
    cudaGetSymbolAddress((void**)&q,   g_q);
    cudaGetSymbolAddress((void**)&k,   g_k);
    cudaGetSymbolAddress((void**)&v,   g_v);
    cudaGetSymbolAddress((void**)&aoh, g_aoh);
    cudaGetSymbolAddress((void**)&aol, g_aol);
    cudaGetSymbolAddress((void**)&wh,  g_wh);
    cudaGetSymbolAddress((void**)&wl,  g_wl);

    ln_kernel<<<NM, 256>>>(x, ln_g, ln_b);

    const int WN = NE * NHD;             // 1M elements per weight
    const float* wsrc[4] = {wq, wk, wv, wo};
    for (int i = 0; i < 4; i++)
        splitw_kernel<<<WN / 1024, 256>>>(wsrc[i], wh + (size_t)i * WN,
                                          wl + (size_t)i * WN);

    cudaFuncSetAttribute(gemm_bf16x3<false>,
                         cudaFuncAttributeMaxDynamicSharedMemorySize, 65536);
    cudaFuncSetAttribute(gemm_bf16x3<true>,
                         cudaFuncAttributeMaxDynamicSharedMemorySize, 65536);

    dim3 gqkv(NHD / 128, NM / 128);
    gemm_bf16x3<false><<<gqkv, 256, 65536>>>(xnh, xnl, wh + 0 * (size_t)WN,
                                             wl + 0 * (size_t)WN, bq, nullptr,
                                             q, NM, NHD, NE);
    gemm_bf16x3<false><<<gqkv, 256, 65536>>>(xnh, xnl, wh + 1 * (size_t)WN,
                                             wl + 1 * (size_t)WN, bk, nullptr,
                                             k, NM, NHD, NE);
    gemm_bf16x3<false><<<gqkv, 256, 65536>>>(xnh, xnl, wh + 2 * (size_t)WN,
                                             wl + 2 * (size_t)WN, bv, nullptr,
                                             v, NM, NHD, NE);

    size_t shmem = (size_t)4 * 64 * LDP * sizeof(float);
    cudaFuncSetAttribute(attn_kernel,
                         cudaFuncAttributeMaxDynamicSharedMemorySize, (int)shmem);
    attn_kernel<<<dim3(NS / 64, NH, NB), 256, shmem>>>();

    gemm_bf16x3<true><<<dim3(NE / 128, NM / 128), 256, 65536>>>(
        aoh, aol, wh + 3 * (size_t)WN, wl + 3 * (size_t)WN, bo, x, out,
        NM, NE, NHD);
}

// round 3
// speedup vs baseline: 3.2242x; 2.0491x over previous
#include <cuda_runtime.h>
#include <cuda_bf16.h>

#define NB 2
#define NS 2048
#define NE 1024
#define NH 16
#define ND 64
#define NM (NB*NS)      // 4096 rows
#define NHD (NH*ND)     // 1024

// ---------------------------------------------------------------------------
// Scratch (__device__ globals; allocation-free rule)
// ---------------------------------------------------------------------------
__device__ __align__(16) __nv_bfloat16 g_xnh[NM*NE];
__device__ __align__(16) __nv_bfloat16 g_xnl[NM*NE];
__device__ __align__(16) __nv_bfloat16 g_qh[NM*NHD];
__device__ __align__(16) __nv_bfloat16 g_ql[NM*NHD];
__device__ __align__(16) __nv_bfloat16 g_kh[NM*NHD];
__device__ __align__(16) __nv_bfloat16 g_kl[NM*NHD];
__device__ __align__(16) __nv_bfloat16 g_vh[NM*NHD];
__device__ __align__(16) __nv_bfloat16 g_vl[NM*NHD];
__device__ __align__(16) __nv_bfloat16 g_aoh[NM*NHD];
__device__ __align__(16) __nv_bfloat16 g_aol[NM*NHD];
__device__ __align__(16) __nv_bfloat16 g_wh[4][NE*NHD];
__device__ __align__(16) __nv_bfloat16 g_wl[4][NE*NHD];

// ---------------------------------------------------------------------------
// PTX helpers
// ---------------------------------------------------------------------------
__device__ __forceinline__ void ldsm4(unsigned r[4], unsigned addr) {
    asm volatile("ldmatrix.sync.aligned.m8n8.x4.shared.b16 {%0,%1,%2,%3}, [%4];"
                 : "=r"(r[0]), "=r"(r[1]), "=r"(r[2]), "=r"(r[3]) : "r"(addr));
}
__device__ __forceinline__ void ldsm4t(unsigned r[4], unsigned addr) {
    asm volatile("ldmatrix.sync.aligned.m8n8.x4.trans.shared.b16 {%0,%1,%2,%3}, [%4];"
                 : "=r"(r[0]), "=r"(r[1]), "=r"(r[2]), "=r"(r[3]) : "r"(addr));
}
__device__ __forceinline__ void mma16816(float d[4], const unsigned a[4],
                                         unsigned b0, unsigned b1) {
    asm volatile("mma.sync.aligned.m16n8k16.row.col.f32.bf16.bf16.f32 "
                 "{%0,%1,%2,%3}, {%4,%5,%6,%7}, {%8,%9}, {%0,%1,%2,%3};"
                 : "+f"(d[0]), "+f"(d[1]), "+f"(d[2]), "+f"(d[3])
                 : "r"(a[0]), "r"(a[1]), "r"(a[2]), "r"(a[3]), "r"(b0), "r"(b1));
}
__device__ __forceinline__ void cpa16(unsigned saddr, const void* g) {
    asm volatile("cp.async.cg.shared.global [%0], [%1], 16;" :: "r"(saddr), "l"(g));
}
__device__ __forceinline__ void cpa_commit() {
    asm volatile("cp.async.commit_group;");
}
__device__ __forceinline__ unsigned packbf2(float a, float b) {
    __nv_bfloat162 t = __floats2bfloat162_rn(a, b);
    return *(unsigned*)&t;
}

// ---------------------------------------------------------------------------
// LayerNorm: one block per row; writes bf16 hi/lo split
// ---------------------------------------------------------------------------
__global__ void __launch_bounds__(256) ln_kernel(const float* __restrict__ x,
                                                 const float* __restrict__ gam,
                                                 const float* __restrict__ bet) {
    int row = blockIdx.x;
    int t = threadIdx.x;
    const float4* xr = (const float4*)(x + (size_t)row * NE);
    float4 xv = xr[t];
    float s  = xv.x + xv.y + xv.z + xv.w;
    float ss = xv.x*xv.x + xv.y*xv.y + xv.z*xv.z + xv.w*xv.w;
    #pragma unroll
    for (int m = 16; m; m >>= 1) {
        s  += __shfl_xor_sync(0xffffffffu, s,  m);
        ss += __shfl_xor_sync(0xffffffffu, ss, m);
    }
    __shared__ float sh1[8], sh2[8];
    if ((t & 31) == 0) { sh1[t >> 5] = s; sh2[t >> 5] = ss; }
    __syncthreads();
    s = 0.f; ss = 0.f;
    #pragma unroll
    for (int w = 0; w < 8; w++) { s += sh1[w]; ss += sh2[w]; }
    float mean = s * (1.f / NE);
    float var  = ss * (1.f / NE) - mean * mean;
    float rstd = rsqrtf(var + 1e-5f);
    float4 gv = ((const float4*)gam)[t];
    float4 bv = ((const float4*)bet)[t];
    float o[4];
    o[0] = (xv.x - mean) * rstd * gv.x + bv.x;
    o[1] = (xv.y - mean) * rstd * gv.y + bv.y;
    o[2] = (xv.z - mean) * rstd * gv.z + bv.z;
    o[3] = (xv.w - mean) * rstd * gv.w + bv.w;
    size_t base = (size_t)row * NE + t * 4;
    #pragma unroll
    for (int j = 0; j < 4; j++) {
        __nv_bfloat16 h = __float2bfloat16_rn(o[j]);
        g_xnh[base + j] = h;
        g_xnl[base + j] = __float2bfloat16_rn(o[j] - __bfloat162float(h));
    }
}

// ---------------------------------------------------------------------------
// Weight split (all 4 weights, one launch): fp32 -> bf16 hi/lo
// ---------------------------------------------------------------------------
__global__ void __launch_bounds__(256) splitw_kernel(
    const float* __restrict__ w0, const float* __restrict__ w1,
    const float* __restrict__ w2, const float* __restrict__ w3) {
    int w = blockIdx.x >> 10;
    const float* src = (w == 0) ? w0 : (w == 1) ? w1 : (w == 2) ? w2 : w3;
    int idx = ((blockIdx.x & 1023) * 256 + threadIdx.x) * 4;
    float4 v = *(const float4*)(src + idx);
    float a[4] = {v.x, v.y, v.z, v.w};
    __nv_bfloat16* dh = g_wh[w];
    __nv_bfloat16* dl = g_wl[w];
    #pragma unroll
    for (int j = 0; j < 4; j++) {
        __nv_bfloat16 h = __float2bfloat16_rn(a[j]);
        dh[idx + j] = h;
        dl[idx + j] = __float2bfloat16_rn(a[j] - __bfloat162float(h));
    }
}

// ---------------------------------------------------------------------------
// bf16x3 tensor-core GEMM. OUTMODE 0: fp32 C = acc+bias(+resid).
// OUTMODE 1: bf16 hi/lo (Ch,Cl) = (acc+bias)*scale.
// 128x128 tile, BK=32, 8 warps, cp.async double buffer, swizzled smem.
// ---------------------------------------------------------------------------
template<int OUTMODE, bool RESID>
__global__ void __launch_bounds__(256) gemm_bf16x3(
    const __nv_bfloat16* __restrict__ Ah, const __nv_bfloat16* __restrict__ Al,
    const __nv_bfloat16* __restrict__ Bh, const __nv_bfloat16* __restrict__ Bl,
    const float* __restrict__ bias, const float* __restrict__ resid,
    float* __restrict__ C, __nv_bfloat16* __restrict__ Ch,
    __nv_bfloat16* __restrict__ Cl, float scale, int M, int N, int K)
{
    extern __shared__ char smraw[];
    unsigned sbase = (unsigned)__cvta_generic_to_shared(smraw);
    int tid = threadIdx.x;
    int bm = blockIdx.y, bn = blockIdx.x;
    int lane = tid & 31, wid = tid >> 5;
    int wm = wid >> 2, wn = wid & 3;

    float acc[4][4][4];
    #pragma unroll
    for (int i = 0; i < 4; i++)
        #pragma unroll
        for (int j = 0; j < 4; j++)
            #pragma unroll
            for (int c = 0; c < 4; c++) acc[i][j][c] = 0.f;

    const int iters = K >> 5;

    auto issue = [&](int buf, int k0) {
        unsigned ab  = sbase + buf * 32768;
        unsigned bbh = ab + 16384;
        unsigned bbl = ab + 24576;
        #pragma unroll
        for (int i = 0; i < 2; i++) {
            int u = tid + i * 256;
            int row = u >> 2, c = u & 3;
            const __nv_bfloat16* ga = Ah + (size_t)(bm * 128 + row) * K + k0 + c * 8;
            const __nv_bfloat16* gl = Al + (size_t)(bm * 128 + row) * K + k0 + c * 8;
            cpa16(ab + row * 128 + ((c ^ (row & 7)) << 4), ga);
            cpa16(ab + row * 128 + (((c + 4) ^ (row & 7)) << 4), gl);
        }
        #pragma unroll
        for (int i = 0; i < 2; i++) {
            int u = tid + i * 256;
            int k = u >> 4, c = u & 15;
            size_t goff = (size_t)(k0 + k) * N + bn * 128 + c * 8;
            unsigned soff = k * 256 + ((c ^ (k & 7)) << 4);
            cpa16(bbh + soff, Bh + goff);
            cpa16(bbl + soff, Bl + goff);
        }
        cpa_commit();
    };

    issue(0, 0);

    int r = lane & 7, sel = lane >> 3;
    for (int it = 0; it < iters; it++) {
        if (it + 1 < iters) {
            issue((it + 1) & 1, (it + 1) << 5);
            asm volatile("cp.async.wait_group 1;");
        } else {
            asm volatile("cp.async.wait_group 0;");
        }
        __syncthreads();

        unsigned ab  = sbase + (it & 1) * 32768;
        unsigned bbh = ab + 16384;
        unsigned bbl = ab + 24576;
        #pragma unroll
        for (int s = 0; s < 2; s++) {
            unsigned aH[4][4], aL[4][4], bHf[2][4], bLf[2][4];
            #pragma unroll
            for (int mf = 0; mf < 4; mf++) {
                int row = wm * 64 + mf * 16 + r + ((sel & 1) << 3);
                int ch = 2 * s + (sel >> 1);
                ldsm4(aH[mf], ab + row * 128 + ((ch ^ (row & 7)) << 4));
                ldsm4(aL[mf], ab + row * 128 + (((ch + 4) ^ (row & 7)) << 4));
            }
            #pragma unroll
            for (int np = 0; np < 2; np++) {
                int k = 16 * s + r + ((sel & 1) << 3);
                int ch = wn * 4 + np * 2 + (sel >> 1);
                unsigned off = k * 256 + ((ch ^ (k & 7)) << 4);
                ldsm4t(bHf[np], bbh + off);
                ldsm4t(bLf[np], bbl + off);
            }
            #pragma unroll
            for (int mf = 0; mf < 4; mf++)
                #pragma unroll
                for (int nf = 0; nf < 4; nf++) {
                    unsigned bh0 = bHf[nf >> 1][(nf & 1) * 2];
                    unsigned bh1 = bHf[nf >> 1][(nf & 1) * 2 + 1];
                    unsigned bl0 = bLf[nf >> 1][(nf & 1) * 2];
                    unsigned bl1 = bLf[nf >> 1][(nf & 1) * 2 + 1];
                    mma16816(acc[mf][nf], aH[mf], bh0, bh1);
                    mma16816(acc[mf][nf], aH[mf], bl0, bl1);
                    mma16816(acc[mf][nf], aL[mf], bh0, bh1);
                }
        }
        __syncthreads();
    }

    int g = lane >> 2, t2 = (lane & 3) * 2;
    #pragma unroll
    for (int mf = 0; mf < 4; mf++) {
        int row0 = bm * 128 + wm * 64 + mf * 16 + g;
        #pragma unroll
        for (int nf = 0; nf < 4; nf++) {
            int col = bn * 128 + wn * 32 + nf * 8 + t2;
            float b0 = bias[col], b1 = bias[col + 1];
            float v00 = acc[mf][nf][0] + b0, v01 = acc[mf][nf][1] + b1;
            float v10 = acc[mf][nf][2] + b0, v11 = acc[mf][nf][3] + b1;
            if (OUTMODE == 0) {
                if (RESID) {
                    const float* rp0 = resid + (size_t)row0 * N + col;
                    const float* rp1 = resid + (size_t)(row0 + 8) * N + col;
                    v00 += rp0[0]; v01 += rp0[1];
                    v10 += rp1[0]; v11 += rp1[1];
                }
                *(float2*)(C + (size_t)row0 * N + col)       = make_float2(v00, v01);
                *(float2*)(C + (size_t)(row0 + 8) * N + col) = make_float2(v10, v11);
            } else {
                v00 *= scale; v01 *= scale; v10 *= scale; v11 *= scale;
                __nv_bfloat162 h0 = __floats2bfloat162_rn(v00, v01);
                __nv_bfloat162 h1 = __floats2bfloat162_rn(v10, v11);
                *(__nv_bfloat162*)(Ch + (size_t)row0 * N + col)       = h0;
                *(__nv_bfloat162*)(Ch + (size_t)(row0 + 8) * N + col) = h1;
                __nv_bfloat162 l0 = __floats2bfloat162_rn(
                    v00 - __bfloat162float(h0.x), v01 - __bfloat162float(h0.y));
                __nv_bfloat162 l1 = __floats2bfloat162_rn(
                    v10 - __bfloat162float(h1.x), v11 - __bfloat162float(h1.y));
                *(__nv_bfloat162*)(Cl + (size_t)row0 * N + col)       = l0;
                *(__nv_bfloat162*)(Cl + (size_t)(row0 + 8) * N + col) = l1;
            }
        }
    }
}

// ---------------------------------------------------------------------------
// Tensor-core causal flash attention. Block = 4 warps, 64 q-rows, per (b,h).
// K/V hi/lo double-buffered smem tiles; P reused in registers.
// Smem: Qh 8K | Ql 8K | 2 x (Kh 8K | Kl 8K | Vh 8K | Vl 8K) = 80KB.
// ---------------------------------------------------------------------------
__global__ void __launch_bounds__(128) attn_tc_kernel() {
    extern __shared__ char smraw[];
    unsigned sb = (unsigned)__cvta_generic_to_shared(smraw);
    int tid = threadIdx.x, lane = tid & 31, wid = tid >> 5;
    int qt = (int)gridDim.x - 1 - (int)blockIdx.x;   // long blocks first
    int h = blockIdx.y, b = blockIdx.z;
    int g = lane >> 2, t2 = (lane & 3) * 2;
    int r8 = lane & 7, sel = lane >> 3;

    size_t qrow0 = (size_t)(b * NS + qt * 64);

    // Stage Q hi/lo (group 1)
    #pragma unroll
    for (int i = 0; i < 4; i++) {
        int u = tid + i * 128;
        int row = u >> 3, c = u & 7;
        size_t go = (qrow0 + row) * NHD + h * ND + c * 8;
        unsigned so = row * 128 + ((c ^ (row & 7)) << 4);
        cpa16(sb + so, g_qh + go);
        cpa16(sb + 8192 + so, g_ql + go);
    }
    cpa_commit();

    auto issueKV = [&](int buf, int kt) {
        unsigned base = sb + 16384 + buf * 32768;
        size_t krow0 = (size_t)(b * NS + kt * 64);
        #pragma unroll
        for (int i = 0; i < 4; i++) {
            int u = tid + i * 128;
            int row = u >> 3, c = u & 7;
            size_t go = (krow0 + row) * NHD + h * ND + c * 8;
            unsigned so = row * 128 + ((c ^ (row & 7)) << 4);
            cpa16(base + so,         g_kh + go);
            cpa16(base + 8192  + so, g_kl + go);
            cpa16(base + 16384 + so, g_vh + go);
            cpa16(base + 24576 + so, g_vl + go);
        }
        cpa_commit();
    };
    issueKV(0, 0);

    // Q fragments (A, m16k16) for 4 k-chunks, hi and lo
    asm volatile("cp.async.wait_group 1;");
    __syncthreads();
    unsigned aQh[4][4], aQl[4][4];
    #pragma unroll
    for (int kc = 0; kc < 4; kc++) {
        int row = wid * 16 + r8 + ((sel & 1) << 3);
        int ch = 2 * kc + (sel >> 1);
        unsigned so = row * 128 + ((ch ^ (row & 7)) << 4);
        ldsm4(aQh[kc], sb + so);
        ldsm4(aQl[kc], sb + 8192 + so);
    }

    float o[8][4];
    #pragma unroll
    for (int d = 0; d < 8; d++)
        #pragma unroll
        for (int c = 0; c < 4; c++) o[d][c] = 0.f;
    float m0 = -3e38f, m1 = -3e38f, l0 = 0.f, l1 = 0.f;

    for (int kt = 0; kt <= qt; kt++) {
        __syncthreads();                 // prev iter done reading next buf
        if (kt < qt) {
            issueKV((kt + 1) & 1, kt + 1);
            asm volatile("cp.async.wait_group 1;");
        } else {
            asm volatile("cp.async.wait_group 0;");
        }
        __syncthreads();
        unsigned kb = sb + 16384 + (kt & 1) * 32768;

        // ---- S = Q K^T (bf16x3) ----
        float s[8][4];
        #pragma unroll
        for (int jf = 0; jf < 8; jf++)
            #pragma unroll
            for (int c = 0; c < 4; c++) s[jf][c] = 0.f;

        #pragma unroll
        for (int kc = 0; kc < 4; kc++) {
            unsigned bh[4][4], bl[4][4];
            #pragma unroll
            for (int jp = 0; jp < 4; jp++) {
                int jrow = jp * 16 + ((sel >> 1) << 3) + r8;
                int ch = 2 * kc + (sel & 1);
                unsigned so = jrow * 128 + ((ch ^ (jrow & 7)) << 4);
                ldsm4(bh[jp], kb + so);
                ldsm4(bl[jp], kb + 8192 + so);
            }
            #pragma unroll
            for (int jf = 0; jf < 8; jf++) {
                unsigned b0 = bh[jf >> 1][(jf & 1) * 2];
                unsigned b1 = bh[jf >> 1][(jf & 1) * 2 + 1];
                unsigned c0 = bl[jf >> 1][(jf & 1) * 2];
                unsigned c1 = bl[jf >> 1][(jf & 1) * 2 + 1];
                mma16816(s[jf], aQh[kc], b0, b1);
                mma16816(s[jf], aQh[kc], c0, c1);
                mma16816(s[jf], aQl[kc], b0, b1);
            }
        }

        // ---- causal mask on diagonal tile ----
        if (kt == qt) {
            int rowg = wid * 16 + g;
            #pragma unroll
            for (int jf = 0; jf < 8; jf++) {
                int col = jf * 8 + t2;
                if (col     > rowg)     s[jf][0] = -1e30f;
                if (col + 1 > rowg)     s[jf][1] = -1e30f;
                if (col     > rowg + 8) s[jf][2] = -1e30f;
                if (col + 1 > rowg + 8) s[jf][3] = -1e30f;
            }
        }

        // ---- online softmax (rows g, g+8; stats across quad lanes) ----
        float mx0 = -1e30f, mx1 = -1e30f;
        #pragma unroll
        for (int jf = 0; jf < 8; jf++) {
            mx0 = fmaxf(mx0, fmaxf(s[jf][0], s[jf][1]));
            mx1 = fmaxf(mx1, fmaxf(s[jf][2], s[jf][3]));
        }
        mx0 = fmaxf(mx0, __shfl_xor_sync(0xffffffffu, mx0, 1));
        mx0 = fmaxf(mx0, __shfl_xor_sync(0xffffffffu, mx0, 2));
        mx1 = fmaxf(mx1, __shfl_xor_sync(0xffffffffu, mx1, 1));
        mx1 = fmaxf(mx1, __shfl_xor_sync(0xffffffffu, mx1, 2));
        float mn0 = fmaxf(m0, mx0), mn1 = fmaxf(m1, mx1);
        float a0 = __expf(m0 - mn0), a1 = __expf(m1 - mn1);
        m0 = mn0; m1 = mn1;

        unsigned ph[4][4], pl[4][4];
        float ps0 = 0.f, ps1 = 0.f;
        #pragma unroll
        for (int jf = 0; jf < 8; jf++) {
            float p0 = __expf(s[jf][0] - mn0);
            float p1 = __expf(s[jf][1] - mn0);
            float p2 = __expf(s[jf][2] - mn1);
            float p3 = __expf(s[jf][3] - mn1);
            ps0 += p0 + p1; ps1 += p2 + p3;
            unsigned hA = packbf2(p0, p1);
            unsigned hB = packbf2(p2, p3);
            __nv_bfloat162 hA2 = *(__nv_bfloat162*)&hA;
            __nv_bfloat162 hB2 = *(__nv_bfloat162*)&hB;
            unsigned lA = packbf2(p0 - __bfloat162float(hA2.x),
                                  p1 - __bfloat162float(hA2.y));
            unsigned lB = packbf2(p2 - __bfloat162float(hB2.x),
                                  p3 - __bfloat162float(hB2.y));
            int kc = jf >> 1, hi = (jf & 1) * 2;
            ph[kc][hi]     = hA; ph[kc][hi + 1] = hB;
            pl[kc][hi]     = lA; pl[kc][hi + 1] = lB;
        }
        ps0 += __shfl_xor_sync(0xffffffffu, ps0, 1);
        ps0 += __shfl_xor_sync(0xffffffffu, ps0, 2);
        ps1 += __shfl_xor_sync(0xffffffffu, ps1, 1);
        ps1 += __shfl_xor_sync(0xffffffffu, ps1, 2);
        l0 = l0 * a0 + ps0;
        l1 = l1 * a1 + ps1;
        #pragma unroll
        for (int d = 0; d < 8; d++) {
            o[d][0] *= a0; o[d][1] *= a0;
            o[d][2] *= a1; o[d][3] *= a1;
        }

        // ---- O += P V (bf16x3) ----
        #pragma unroll
        for (int kc = 0; kc < 4; kc++) {
            unsigned vh[4][4], vl[4][4];
            #pragma unroll
            for (int np = 0; np < 4; np++) {
                int krow = kc * 16 + (lane & 15);
                int ch = np * 2 + (lane >> 4);
                unsigned so = krow * 128 + ((ch ^ (krow & 7)) << 4);
                ldsm4t(vh[np], kb + 16384 + so);
                ldsm4t(vl[np], kb + 24576 + so);
            }
            #pragma unroll
            for (int df = 0; df < 8; df++) {
                unsigned b0 = vh[df >> 1][(df & 1) * 2];
                unsigned b1 = vh[df >> 1][(df & 1) * 2 + 1];
                unsigned c0 = vl[df >> 1][(df & 1) * 2];
                unsigned c1 = vl[df >> 1][(df & 1) * 2 + 1];
                mma16816(o[df], ph[kc], b0, b1);
                mma16816(o[df], ph[kc], c0, c1);
                mma16816(o[df], pl[kc], b0, b1);
            }
        }
    }

    // ---- epilogue: normalize, split to bf16 hi/lo ----
    float inv0 = 1.f / l0, inv1 = 1.f / l1;
    size_t row0 = qrow0 + wid * 16 + g;
    #pragma unroll
    for (int df = 0; df < 8; df++) {
        int col = h * ND + df * 8 + t2;
        float v00 = o[df][0] * inv0, v01 = o[df][1] * inv0;
        float v10 = o[df][2] * inv1, v11 = o[df][3] * inv1;
        __nv_bfloat162 h0 = __floats2bfloat162_rn(v00, v01);
        __nv_bfloat162 h1 = __floats2bfloat162_rn(v10, v11);
        *(__nv_bfloat162*)(g_aoh + row0 * NHD + col)       = h0;
        *(__nv_bfloat162*)(g_aoh + (row0 + 8) * NHD + col) = h1;
        __nv_bfloat162 L0 = __floats2bfloat162_rn(
            v00 - __bfloat162float(h0.x), v01 - __bfloat162float(h0.y));
        __nv_bfloat162 L1 = __floats2bfloat162_rn(
            v10 - __bfloat162float(h1.x), v11 - __bfloat162float(h1.y));
        *(__nv_bfloat162*)(g_aol + row0 * NHD + col)       = L0;
        *(__nv_bfloat162*)(g_aol + (row0 + 8) * NHD + col) = L1;
    }
}

// ---------------------------------------------------------------------------
// Launch
// ---------------------------------------------------------------------------
extern "C" void kernel_launch(void* const* d_in, const int* in_sizes, int n_in,
                              void* d_out, int out_size) {
    const float* x    = (const float*)d_in[0];
    const float* ln_g = (const float*)d_in[1];
    const float* ln_b = (const float*)d_in[2];
    const float* wq   = (const float*)d_in[3];
    const float* bq   = (const float*)d_in[4];
    const float* wk   = (const float*)d_in[5];
    const float* bk   = (const float*)d_in[6];
    const float* wv   = (const float*)d_in[7];
    const float* bv   = (const float*)d_in[8];
    const float* wo   = (const float*)d_in[9];
    const float* bo   = (const float*)d_in[10];
    float* out = (float*)d_out;

    __nv_bfloat16 *xnh, *xnl, *qh, *ql, *kh, *kl, *vh, *vl, *aoh, *aol, *wh, *wl;
    cudaGetSymbolAddress((void**)&xnh, g_xnh);
    cudaGetSymbolAddress((void**)&xnl, g_xnl);
    cudaGetSymbolAddress((void**)&qh,  g_qh);
    cudaGetSymbolAddress((void**)&ql,  g_ql);
    cudaGetSymbolAddress((void**)&kh,  g_kh);
    cudaGetSymbolAddress((void**)&kl,  g_kl);
    cudaGetSymbolAddress((void**)&vh,  g_vh);
    cudaGetSymbolAddress((void**)&vl,  g_vl);
    cudaGetSymbolAddress((void**)&aoh, g_aoh);
    cudaGetSymbolAddress((void**)&aol, g_aol);
    cudaGetSymbolAddress((void**)&wh,  g_wh);
    cudaGetSymbolAddress((void**)&wl,  g_wl);

    ln_kernel<<<NM, 256>>>(x, ln_g, ln_b);
    splitw_kernel<<<4096, 256>>>(wq, wk, wv, wo);

    cudaFuncSetAttribute(gemm_bf16x3<0, true>,
                         cudaFuncAttributeMaxDynamicSharedMemorySize, 65536);
    cudaFuncSetAttribute(gemm_bf16x3<1, false>,
                         cudaFuncAttributeMaxDynamicSharedMemorySize, 65536);

    const size_t WN = (size_t)NE * NHD;
    dim3 gqkv(NHD / 128, NM / 128);
    gemm_bf16x3<1, false><<<gqkv, 256, 65536>>>(
        xnh, xnl, wh + 0 * WN, wl + 0 * WN, bq, nullptr,
        nullptr, qh, ql, 0.125f, NM, NHD, NE);
    gemm_bf16x3<1, false><<<gqkv, 256, 65536>>>(
        xnh, xnl, wh + 1 * WN, wl + 1 * WN, bk, nullptr,
        nullptr, kh, kl, 1.0f, NM, NHD, NE);
    gemm_bf16x3<1, false><<<gqkv, 256, 65536>>>(
        xnh, xnl, wh + 2 * WN, wl + 2 * WN, bv, nullptr,
        nullptr, vh, vl, 1.0f, NM, NHD, NE);

    cudaFuncSetAttribute(attn_tc_kernel,
                         cudaFuncAttributeMaxDynamicSharedMemorySize, 81920);
    attn_tc_kernel<<<dim3(NS / 64, NH, NB), 128, 81920>>>();

    gemm_bf16x3<0, true><<<dim3(NE / 128, NM / 128), 256, 65536>>>(
        aoh, aol, wh + 3 * WN, wl + 3 * WN, bo, x,
        out, nullptr, nullptr, 1.0f, NM, NE, NHD);
}

// round 5
// speedup vs baseline: 4.0376x; 1.2523x over previous
#include <cuda_runtime.h>
#include <cuda_fp16.h>
#include <cstdint>

#define NB 2
#define NS 2048
#define NE 1024
#define NH 16
#define ND 64
#define NM (NB*NS)      // 4096 rows
#define NHD (NH*ND)     // 1024

// ---------------------------------------------------------------------------
// Scratch (__device__ globals; allocation-free rule)
// ---------------------------------------------------------------------------
__device__ __align__(16) __half g_xnh[NM*NE];          // LN out, fp16 hi only
__device__ __align__(16) __half g_qh[NM*NHD];          // q (pre-scaled), hi only
__device__ __align__(16) __half g_kh[NM*NHD];
__device__ __align__(16) __half g_kl[NM*NHD];
__device__ __align__(16) __half g_vh[NM*NHD];
__device__ __align__(16) __half g_vl[NM*NHD];
__device__ __align__(16) __half g_aoh[NM*NHD];         // attention out, hi only
// weights TRANSPOSED: [N][K] K-major; [0..2] = q,k,v (contiguous 3072 rows), [3] = o
__device__ __align__(16) __half g_wh[4][NE*NHD];
__device__ __align__(16) __half g_wl[4][NE*NHD];

// ---------------------------------------------------------------------------
// PTX helpers
// ---------------------------------------------------------------------------
__device__ __forceinline__ void ldsm4(unsigned r[4], unsigned addr) {
    asm volatile("ldmatrix.sync.aligned.m8n8.x4.shared.b16 {%0,%1,%2,%3}, [%4];"
                 : "=r"(r[0]), "=r"(r[1]), "=r"(r[2]), "=r"(r[3]) : "r"(addr));
}
__device__ __forceinline__ void ldsm4t(unsigned r[4], unsigned addr) {
    asm volatile("ldmatrix.sync.aligned.m8n8.x4.trans.shared.b16 {%0,%1,%2,%3}, [%4];"
                 : "=r"(r[0]), "=r"(r[1]), "=r"(r[2]), "=r"(r[3]) : "r"(addr));
}
__device__ __forceinline__ void mmaf16(float d[4], const unsigned a[4],
                                       unsigned b0, unsigned b1) {
    asm volatile("mma.sync.aligned.m16n8k16.row.col.f32.f16.f16.f32 "
                 "{%0,%1,%2,%3}, {%4,%5,%6,%7}, {%8,%9}, {%0,%1,%2,%3};"
                 : "+f"(d[0]), "+f"(d[1]), "+f"(d[2]), "+f"(d[3])
                 : "r"(a[0]), "r"(a[1]), "r"(a[2]), "r"(a[3]), "r"(b0), "r"(b1));
}
__device__ __forceinline__ void cpa16(unsigned saddr, const void* g) {
    asm volatile("cp.async.cg.shared.global [%0], [%1], 16;" :: "r"(saddr), "l"(g));
}
__device__ __forceinline__ void cpa_commit() {
    asm volatile("cp.async.commit_group;");
}
__device__ __forceinline__ unsigned packh2(float a, float b) {
    __half2 t = __floats2half2_rn(a, b);
    return *(unsigned*)&t;
}

// ---------------------------------------------------------------------------
// LayerNorm: one block per row; fp16 hi output only
// ---------------------------------------------------------------------------
__global__ void __launch_bounds__(256) ln_kernel(const float* __restrict__ x,
                                                 const float* __restrict__ gam,
                                                 const float* __restrict__ bet) {
    int row = blockIdx.x;
    int t = threadIdx.x;
    const float4* xr = (const float4*)(x + (size_t)row * NE);
    float4 xv = xr[t];
    float s  = xv.x + xv.y + xv.z + xv.w;
    float ss = xv.x*xv.x + xv.y*xv.y + xv.z*xv.z + xv.w*xv.w;
    #pragma unroll
    for (int m = 16; m; m >>= 1) {
        s  += __shfl_xor_sync(0xffffffffu, s,  m);
        ss += __shfl_xor_sync(0xffffffffu, ss, m);
    }
    __shared__ float sh1[8], sh2[8];
    if ((t & 31) == 0) { sh1[t >> 5] = s; sh2[t >> 5] = ss; }
    __syncthreads();
    s = 0.f; ss = 0.f;
    #pragma unroll
    for (int w = 0; w < 8; w++) { s += sh1[w]; ss += sh2[w]; }
    float mean = s * (1.f / NE);
    float var  = ss * (1.f / NE) - mean * mean;
    float rstd = rsqrtf(var + 1e-5f);
    float4 gv = ((const float4*)gam)[t];
    float4 bv = ((const float4*)bet)[t];
    __half2 o0 = __floats2half2_rn((xv.x - mean) * rstd * gv.x + bv.x,
                                   (xv.y - mean) * rstd * gv.y + bv.y);
    __half2 o1 = __floats2half2_rn((xv.z - mean) * rstd * gv.z + bv.z,
                                   (xv.w - mean) * rstd * gv.w + bv.w);
    __half2* dst = (__half2*)(g_xnh + (size_t)row * NE + t * 4);
    dst[0] = o0; dst[1] = o1;
}

// ---------------------------------------------------------------------------
// Weight split + TRANSPOSE: W[K,N] fp32 -> Wt[N,K] fp16 hi/lo
// ---------------------------------------------------------------------------
__global__ void __launch_bounds__(256) splitwT_kernel(
    const float* __restrict__ w0, const float* __restrict__ w1,
    const float* __restrict__ w2, const float* __restrict__ w3) {
    int w = blockIdx.z;
    const float* src = (w == 0) ? w0 : (w == 1) ? w1 : (w == 2) ? w2 : w3;
    __shared__ float tile[32][33];
    int kb = blockIdx.x * 32, nb = blockIdx.y * 32;
    int tx = threadIdx.x & 31, ty = threadIdx.x >> 5;
    #pragma unroll
    for (int i = 0; i < 32; i += 8)
        tile[ty + i][tx] = src[(size_t)(kb + ty + i) * NHD + nb + tx];
    __syncthreads();
    __half* dh = g_wh[w];
    __half* dl = g_wl[w];
    #pragma unroll
    for (int i = 0; i < 32; i += 8) {
        float v = tile[tx][ty + i];            // = W[kb+tx][nb+ty+i]
        int n = nb + ty + i, k = kb + tx;
        __half h = __float2half_rn(v);
        dh[(size_t)n * NE + k] = h;
        dl[(size_t)n * NE + k] = __float2half_rn(v - __half2float(h));
    }
}

// ---------------------------------------------------------------------------
// fp16 2-chain GEMM: D = Ah @ (Bh+Bl)^T. A[M,K] K-major hi; B[N,K] K-major.
// 128x128 tile, BK=64, 8 warps (2x4), cp.async double buffer (2x48KB).
// MODE 0: WO — fp32 C = D + bias0 + resid.
// MODE 1: fused QKV (N=3072) — q: fp16 hi *0.125; k,v: fp16 hi/lo.
// ---------------------------------------------------------------------------
template<int MODE>
__global__ void __launch_bounds__(256) gemm_f16(
    const __half* __restrict__ A, const __half* __restrict__ Bh,
    const __half* __restrict__ Bl,
    const float* __restrict__ bias0, const float* __restrict__ bias1,
    const float* __restrict__ bias2, const float* __restrict__ resid,
    float* __restrict__ C)
{
    extern __shared__ char smraw[];
    unsigned sa = (unsigned)__cvta_generic_to_shared(smraw);
    int tid = threadIdx.x;
    int bm = blockIdx.y, bn = blockIdx.x;
    int lane = tid & 31, wid = tid >> 5;
    int wm = wid >> 2, wn = wid & 3;

    float acc[4][4][4];
    #pragma unroll
    for (int i = 0; i < 4; i++)
        #pragma unroll
        for (int j = 0; j < 4; j++)
            #pragma unroll
            for (int c = 0; c < 4; c++) acc[i][j][c] = 0.f;

    auto issue = [&](int buf, int k0) {
        unsigned base = sa + buf * 49152;
        #pragma unroll
        for (int i = 0; i < 4; i++) {
            int u = tid + i * 256;
            int row = u >> 3, c = u & 7;
            unsigned so = row * 128 + ((c ^ (row & 7)) << 4);
            cpa16(base + so,         A  + (size_t)(bm * 128 + row) * NE + k0 + c * 8);
            cpa16(base + 16384 + so, Bh + (size_t)(bn * 128 + row) * NE + k0 + c * 8);
            cpa16(base + 32768 + so, Bl + (size_t)(bn * 128 + row) * NE + k0 + c * 8);
        }
        cpa_commit();
    };

    const int iters = NE >> 6;      // K = 1024, BK = 64
    issue(0, 0);

    int r8 = lane & 7, sel = lane >> 3;
    for (int it = 0; it < iters; it++) {
        if (it + 1 < iters) {
            issue((it + 1) & 1, (it + 1) << 6);
            asm volatile("cp.async.wait_group 1;");
        } else {
            asm volatile("cp.async.wait_group 0;");
        }
        __syncthreads();

        unsigned ab  = sa + (it & 1) * 49152;
        unsigned bbh = ab + 16384;
        unsigned bbl = ab + 32768;
        #pragma unroll
        for (int s = 0; s < 4; s++) {
            int ch = 2 * s + (sel >> 1);
            unsigned aH[4][4], bH[2][4], bL[2][4];
            #pragma unroll
            for (int mf = 0; mf < 4; mf++) {
                int row = wm * 64 + mf * 16 + r8 + ((sel & 1) << 3);
                ldsm4(aH[mf], ab + row * 128 + ((ch ^ (row & 7)) << 4));
            }
            #pragma unroll
            for (int np = 0; np < 2; np++) {
                int nrow = wn * 32 + np * 16 + r8 + ((sel & 1) << 3);
                unsigned so = nrow * 128 + ((ch ^ (nrow & 7)) << 4);
                ldsm4(bH[np], bbh + so);
                ldsm4(bL[np], bbl + so);
            }
            #pragma unroll
            for (int mf = 0; mf < 4; mf++)
                #pragma unroll
                for (int nf = 0; nf < 4; nf++) {
                    mmaf16(acc[mf][nf], aH[mf],
                           bH[nf >> 1][nf & 1], bH[nf >> 1][(nf & 1) + 2]);
                    mmaf16(acc[mf][nf], aH[mf],
                           bL[nf >> 1][nf & 1], bL[nf >> 1][(nf & 1) + 2]);
                }
        }
        __syncthreads();
    }

    int g = lane >> 2, t2 = (lane & 3) * 2;
    if (MODE == 0) {
        #pragma unroll
        for (int mf = 0; mf < 4; mf++) {
            int row0 = bm * 128 + wm * 64 + mf * 16 + g;
            #pragma unroll
            for (int nf = 0; nf < 4; nf++) {
                int col = bn * 128 + wn * 32 + nf * 8 + t2;
                float b0 = bias0[col], b1 = bias0[col + 1];
                const float* rp0 = resid + (size_t)row0 * NHD + col;
                const float* rp1 = resid + (size_t)(row0 + 8) * NHD + col;
                *(float2*)(C + (size_t)row0 * NHD + col) =
                    make_float2(acc[mf][nf][0] + b0 + rp0[0],
                                acc[mf][nf][1] + b1 + rp0[1]);
                *(float2*)(C + (size_t)(row0 + 8) * NHD + col) =
                    make_float2(acc[mf][nf][2] + b0 + rp1[0],
                                acc[mf][nf][3] + b1 + rp1[1]);
            }
        }
    } else {
        int which = bn >> 3;                  // 0:q 1:k 2:v (1024/128 = 8 tiles)
        const float* bias = (which == 0) ? bias0 : (which == 1) ? bias1 : bias2;
        float scl = (which == 0) ? 0.125f : 1.0f;
        __half* Ch = (which == 0) ? g_qh : (which == 1) ? g_kh : g_vh;
        __half* Cl = (which == 1) ? g_kl : g_vl;   // unused for q
        #pragma unroll
        for (int mf = 0; mf < 4; mf++) {
            int row0 = bm * 128 + wm * 64 + mf * 16 + g;
            #pragma unroll
            for (int nf = 0; nf < 4; nf++) {
                int col = (bn & 7) * 128 + wn * 32 + nf * 8 + t2;
                int bcol = col;
                float v00 = (acc[mf][nf][0] + bias[bcol])     * scl;
                float v01 = (acc[mf][nf][1] + bias[bcol + 1]) * scl;
                float v10 = (acc[mf][nf][2] + bias[bcol])     * scl;
                float v11 = (acc[mf][nf][3] + bias[bcol + 1]) * scl;
                __half2 h0 = __floats2half2_rn(v00, v01);
                __half2 h1 = __floats2half2_rn(v10, v11);
                *(__half2*)(Ch + (size_t)row0 * NHD + col)       = h0;
                *(__half2*)(Ch + (size_t)(row0 + 8) * NHD + col) = h1;
                if (which != 0) {
                    __half2 l0 = __floats2half2_rn(v00 - __half2float(h0.x),
                                                   v01 - __half2float(h0.y));
                    __half2 l1 = __floats2half2_rn(v10 - __half2float(h1.x),
                                                   v11 - __half2float(h1.y));
                    *(__half2*)(Cl + (size_t)row0 * NHD + col)       = l0;
                    *(__half2*)(Cl + (size_t)(row0 + 8) * NHD + col) = l1;
                }
            }
        }
    }
}

// ---------------------------------------------------------------------------
// fp16 2-chain tensor-core causal flash attention.
// Block = 4 warps, 64 q-rows, per (b,h). Q hi only; K,V hi/lo double-buffered.
// Smem: Q 8K | 2 x (Kh 8K | Kl 8K | Vh 8K | Vl 8K) = 72KB.
// ---------------------------------------------------------------------------
__global__ void __launch_bounds__(128) attn_tc_kernel() {
    extern __shared__ char smraw[];
    unsigned sb = (unsigned)__cvta_generic_to_shared(smraw);
    int tid = threadIdx.x, lane = tid & 31, wid = tid >> 5;
    int qt = (int)gridDim.x - 1 - (int)blockIdx.x;   // long blocks first
    int h = blockIdx.y, b = blockIdx.z;
    int g = lane >> 2, t2 = (lane & 3) * 2;
    int r8 = lane & 7, sel = lane >> 3;

    size_t qrow0 = (size_t)(b * NS + qt * 64);

    // Stage Q hi (group 1)
    #pragma unroll
    for (int i = 0; i < 4; i++) {
        int u = tid + i * 128;
        int row = u >> 3, c = u & 7;
        size_t go = (qrow0 + row) * NHD + h * ND + c * 8;
        cpa16(sb + row * 128 + ((c ^ (row & 7)) << 4), g_qh + go);
    }
    cpa_commit();

    auto issueKV = [&](int buf, int kt) {
        unsigned base = sb + 8192 + buf * 32768;
        size_t krow0 = (size_t)(b * NS + kt * 64);
        #pragma unroll
        for (int i = 0; i < 4; i++) {
            int u = tid + i * 128;
            int row = u >> 3, c = u & 7;
            size_t go = (krow0 + row) * NHD + h * ND + c * 8;
            unsigned so = row * 128 + ((c ^ (row & 7)) << 4);
            cpa16(base + so,         g_kh + go);
            cpa16(base + 8192  + so, g_kl + go);
            cpa16(base + 16384 + so, g_vh + go);
            cpa16(base + 24576 + so, g_vl + go);
        }
        cpa_commit();
    };
    issueKV(0, 0);

    // Q fragments (A, m16k16), 4 k-chunks
    asm volatile("cp.async.wait_group 1;");
    __syncthreads();
    unsigned aQ[4][4];
    #pragma unroll
    for (int kc = 0; kc < 4; kc++) {
        int row = wid * 16 + r8 + ((sel & 1) << 3);
        int ch = 2 * kc + (sel >> 1);
        ldsm4(aQ[kc], sb + row * 128 + ((ch ^ (row & 7)) << 4));
    }

    float o[8][4];
    #pragma unroll
    for (int d = 0; d < 8; d++)
        #pragma unroll
        for (int c = 0; c < 4; c++) o[d][c] = 0.f;
    float m0 = -3e38f, m1 = -3e38f, l0 = 0.f, l1 = 0.f;

    for (int kt = 0; kt <= qt; kt++) {
        __syncthreads();
        if (kt < qt) {
            issueKV((kt + 1) & 1, kt + 1);
            asm volatile("cp.async.wait_group 1;");
        } else {
            asm volatile("cp.async.wait_group 0;");
        }
        __syncthreads();
        unsigned kb = sb + 8192 + (kt & 1) * 32768;

        // ---- S = Q K^T (2-chain: Qh*Kh + Qh*Kl) ----
        float s[8][4];
        #pragma unroll
        for (int jf = 0; jf < 8; jf++)
            #pragma unroll
            for (int c = 0; c < 4; c++) s[jf][c] = 0.f;

        #pragma unroll
        for (int kc = 0; kc < 4; kc++) {
            unsigned bh[4][4], bl[4][4];
            #pragma unroll
            for (int jp = 0; jp < 4; jp++) {
                int jrow = jp * 16 + ((sel >> 1) << 3) + r8;
                int ch = 2 * kc + (sel & 1);
                unsigned so = jrow * 128 + ((ch ^ (jrow & 7)) << 4);
                ldsm4(bh[jp], kb + so);
                ldsm4(bl[jp], kb + 8192 + so);
            }
            #pragma unroll
            for (int jf = 0; jf < 8; jf++) {
                mmaf16(s[jf], aQ[kc],
                       bh[jf >> 1][(jf & 1) * 2], bh[jf >> 1][(jf & 1) * 2 + 1]);
                mmaf16(s[jf], aQ[kc],
                       bl[jf >> 1][(jf & 1) * 2], bl[jf >> 1][(jf & 1) * 2 + 1]);
            }
        }

        // ---- causal mask on diagonal tile ----
        if (kt == qt) {
            int rowg = wid * 16 + g;
            #pragma unroll
            for (int jf = 0; jf < 8; jf++) {
                int col = jf * 8 + t2;
                if (col     > rowg)     s[jf][0] = -1e30f;
                if (col + 1 > rowg)     s[jf][1] = -1e30f;
                if (col     > rowg + 8) s[jf][2] = -1e30f;
                if (col + 1 > rowg + 8) s[jf][3] = -1e30f;
            }
        }

        // ---- online softmax ----
        float mx0 = -1e30f, mx1 = -1e30f;
        #pragma unroll
        for (int jf = 0; jf < 8; jf++) {
            mx0 = fmaxf(mx0, fmaxf(s[jf][0], s[jf][1]));
            mx1 = fmaxf(mx1, fmaxf(s[jf][2], s[jf][3]));
        }
        mx0 = fmaxf(mx0, __shfl_xor_sync(0xffffffffu, mx0, 1));
        mx0 = fmaxf(mx0, __shfl_xor_sync(0xffffffffu, mx0, 2));
        mx1 = fmaxf(mx1, __shfl_xor_sync(0xffffffffu, mx1, 1));
        mx1 = fmaxf(mx1, __shfl_xor_sync(0xffffffffu, mx1, 2));
        float mn0 = fmaxf(m0, mx0), mn1 = fmaxf(m1, mx1);
        float a0 = __expf(m0 - mn0), a1 = __expf(m1 - mn1);
        m0 = mn0; m1 = mn1;

        unsigned ph[4][4];
        float ps0 = 0.f, ps1 = 0.f;
        #pragma unroll
        for (int jf = 0; jf < 8; jf++) {
            float p0 = __expf(s[jf][0] - mn0);
            float p1 = __expf(s[jf][1] - mn0);
            float p2 = __expf(s[jf][2] - mn1);
            float p3 = __expf(s[jf][3] - mn1);
            ps0 += p0 + p1; ps1 += p2 + p3;
            int kc = jf >> 1, hi = (jf & 1) * 2;
            ph[kc][hi]     = packh2(p0, p1);
            ph[kc][hi + 1] = packh2(p2, p3);
        }
        ps0 += __shfl_xor_sync(0xffffffffu, ps0, 1);
        ps0 += __shfl_xor_sync(0xffffffffu, ps0, 2);
        ps1 += __shfl_xor_sync(0xffffffffu, ps1, 1);
        ps1 += __shfl_xor_sync(0xffffffffu, ps1, 2);
        l0 = l0 * a0 + ps0;
        l1 = l1 * a1 + ps1;
        #pragma unroll
        for (int d = 0; d < 8; d++) {
            o[d][0] *= a0; o[d][1] *= a0;
            o[d][2] *= a1; o[d][3] *= a1;
        }

        // ---- O += P V (2-chain: Ph*Vh + Ph*Vl) ----
        #pragma unroll
        for (int kc = 0; kc < 4; kc++) {
            unsigned vh[4][4], vl[4][4];
            #pragma unroll
            for (int np = 0; np < 4; np++) {
                int krow = kc * 16 + (lane & 15);
                int ch = np * 2 + (lane >> 4);
                unsigned so = krow * 128 + ((ch ^ (krow & 7)) << 4);
                ldsm4t(vh[np], kb + 16384 + so);
                ldsm4t(vl[np], kb + 24576 + so);
            }
            #pragma unroll
            for (int df = 0; df < 8; df++) {
                mmaf16(o[df], ph[kc],
                       vh[df >> 1][(df & 1) * 2], vh[df >> 1][(df & 1) * 2 + 1]);
                mmaf16(o[df], ph[kc],
                       vl[df >> 1][(df & 1) * 2], vl[df >> 1][(df & 1) * 2 + 1]);
            }
        }
    }

    // ---- epilogue: normalize, fp16 hi out ----
    float inv0 = 1.f / l0, inv1 = 1.f / l1;
    size_t row0 = qrow0 + wid * 16 + g;
    #pragma unroll
    for (int df = 0; df < 8; df++) {
        int col = h * ND + df * 8 + t2;
        *(__half2*)(g_aoh + row0 * NHD + col) =
            __floats2half2_rn(o[df][0] * inv0, o[df][1] * inv0);
        *(__half2*)(g_aoh + (row0 + 8) * NHD + col) =
            __floats2half2_rn(o[df][2] * inv1, o[df][3] * inv1);
    }
}

// ---------------------------------------------------------------------------
// Launch
// ---------------------------------------------------------------------------
extern "C" void kernel_launch(void* const* d_in, const int* in_sizes, int n_in,
                              void* d_out, int out_size) {
    const float* x    = (const float*)d_in[0];
    const float* ln_g = (const float*)d_in[1];
    const float* ln_b = (const float*)d_in[2];
    const float* wq   = (const float*)d_in[3];
    const float* bq   = (const float*)d_in[4];
    const float* wk   = (const float*)d_in[5];
    const float* bk   = (const float*)d_in[6];
    const float* wv   = (const float*)d_in[7];
    const float* bv   = (const float*)d_in[8];
    const float* wo   = (const float*)d_in[9];
    const float* bo   = (const float*)d_in[10];
    float* out = (float*)d_out;

    __half *xnh, *aoh, *wh, *wl;
    cudaGetSymbolAddress((void**)&xnh, g_xnh);
    cudaGetSymbolAddress((void**)&aoh, g_aoh);
    cudaGetSymbolAddress((void**)&wh,  g_wh);
    cudaGetSymbolAddress((void**)&wl,  g_wl);

    ln_kernel<<<NM, 256>>>(x, ln_g, ln_b);
    splitwT_kernel<<<dim3(32, 32, 4), 256>>>(wq, wk, wv, wo);

    const int GSM = 98304;   // 2 x 48KB stages
    cudaFuncSetAttribute(gemm_f16<0>,
                         cudaFuncAttributeMaxDynamicSharedMemorySize, GSM);
    cudaFuncSetAttribute(gemm_f16<1>,
                         cudaFuncAttributeMaxDynamicSharedMemorySize, GSM);

    const size_t WN = (size_t)NE * NHD;
    // fused QKV: B rows 0..3071 span g_wh[0..2] (contiguous)
    gemm_f16<1><<<dim3(3 * NHD / 128, NM / 128), 256, GSM>>>(
        xnh, wh, wl, bq, bk, bv, nullptr, nullptr);

    cudaFuncSetAttribute(attn_tc_kernel,
                         cudaFuncAttributeMaxDynamicSharedMemorySize, 73728);
    attn_tc_kernel<<<dim3(NS / 64, NH, NB), 128, 73728>>>();

    gemm_f16<0><<<dim3(NE / 128, NM / 128), 256, GSM>>>(
        aoh, wh + 3 * WN, wl + 3 * WN, bo, nullptr, nullptr, x, out);
}

// round 6
// speedup vs baseline: 6.2113x; 1.5384x over previous
#include <cuda_runtime.h>
#include <cuda_fp16.h>
#include <cstdint>

#define NB 2
#define NS 2048
#define NE 1024
#define NH 16
#define ND 64
#define NM (NB*NS)      // 4096 rows
#define NHD (NH*ND)     // 1024

// ---------------------------------------------------------------------------
// Scratch (__device__ globals; allocation-free rule)
// ---------------------------------------------------------------------------
__device__ __align__(16) __half g_xnh[NM*NE];          // LN out, fp16
__device__ __align__(16) __half g_qh[NM*NHD];          // q (pre-scaled by 1/8)
__device__ __align__(16) __half g_kh[NM*NHD];
__device__ __align__(16) __half g_vh[NM*NHD];
__device__ __align__(16) __half g_aoh[NM*NHD];         // attention out
// weights TRANSPOSED: [N][K] K-major; [0..2] = q,k,v (contiguous), [3] = o
__device__ __align__(16) __half g_wh[4][NE*NHD];
__device__ __align__(16) __half g_wl[NE*NHD];          // lo split for wo only

// ---------------------------------------------------------------------------
// PTX helpers
// ---------------------------------------------------------------------------
__device__ __forceinline__ void ldsm4(unsigned r[4], unsigned addr) {
    asm volatile("ldmatrix.sync.aligned.m8n8.x4.shared.b16 {%0,%1,%2,%3}, [%4];"
                 : "=r"(r[0]), "=r"(r[1]), "=r"(r[2]), "=r"(r[3]) : "r"(addr));
}
__device__ __forceinline__ void ldsm4t(unsigned r[4], unsigned addr) {
    asm volatile("ldmatrix.sync.aligned.m8n8.x4.trans.shared.b16 {%0,%1,%2,%3}, [%4];"
                 : "=r"(r[0]), "=r"(r[1]), "=r"(r[2]), "=r"(r[3]) : "r"(addr));
}
__device__ __forceinline__ void mmaf16(float d[4], const unsigned a[4],
                                       unsigned b0, unsigned b1) {
    asm volatile("mma.sync.aligned.m16n8k16.row.col.f32.f16.f16.f32 "
                 "{%0,%1,%2,%3}, {%4,%5,%6,%7}, {%8,%9}, {%0,%1,%2,%3};"
                 : "+f"(d[0]), "+f"(d[1]), "+f"(d[2]), "+f"(d[3])
                 : "r"(a[0]), "r"(a[1]), "r"(a[2]), "r"(a[3]), "r"(b0), "r"(b1));
}
__device__ __forceinline__ void cpa16(unsigned saddr, const void* g) {
    asm volatile("cp.async.cg.shared.global [%0], [%1], 16;" :: "r"(saddr), "l"(g));
}
__device__ __forceinline__ void cpa_commit() {
    asm volatile("cp.async.commit_group;");
}
__device__ __forceinline__ unsigned packh2(float a, float b) {
    __half2 t = __floats2half2_rn(a, b);
    return *(unsigned*)&t;
}

// ---------------------------------------------------------------------------
// LayerNorm: one block per row; fp16 output
// ---------------------------------------------------------------------------
__global__ void __launch_bounds__(256) ln_kernel(const float* __restrict__ x,
                                                 const float* __restrict__ gam,
                                                 const float* __restrict__ bet) {
    int row = blockIdx.x;
    int t = threadIdx.x;
    const float4* xr = (const float4*)(x + (size_t)row * NE);
    float4 xv = xr[t];
    float s  = xv.x + xv.y + xv.z + xv.w;
    float ss = xv.x*xv.x + xv.y*xv.y + xv.z*xv.z + xv.w*xv.w;
    #pragma unroll
    for (int m = 16; m; m >>= 1) {
        s  += __shfl_xor_sync(0xffffffffu, s,  m);
        ss += __shfl_xor_sync(0xffffffffu, ss, m);
    }
    __shared__ float sh1[8], sh2[8];
    if ((t & 31) == 0) { sh1[t >> 5] = s; sh2[t >> 5] = ss; }
    __syncthreads();
    s = 0.f; ss = 0.f;
    #pragma unroll
    for (int w = 0; w < 8; w++) { s += sh1[w]; ss += sh2[w]; }
    float mean = s * (1.f / NE);
    float var  = ss * (1.f / NE) - mean * mean;
    float rstd = rsqrtf(var + 1e-5f);
    float4 gv = ((const float4*)gam)[t];
    float4 bv = ((const float4*)bet)[t];
    __half2 o0 = __floats2half2_rn((xv.x - mean) * rstd * gv.x + bv.x,
                                   (xv.y - mean) * rstd * gv.y + bv.y);
    __half2 o1 = __floats2half2_rn((xv.z - mean) * rstd * gv.z + bv.z,
                                   (xv.w - mean) * rstd * gv.w + bv.w);
    __half2* dst = (__half2*)(g_xnh + (size_t)row * NE + t * 4);
    dst[0] = o0; dst[1] = o1;
}

// ---------------------------------------------------------------------------
// Weight split + TRANSPOSE: W[K,N] fp32 -> Wt[N,K] fp16 (lo only for wo)
// ---------------------------------------------------------------------------
__global__ void __launch_bounds__(256) splitwT_kernel(
    const float* __restrict__ w0, const float* __restrict__ w1,
    const float* __restrict__ w2, const float* __restrict__ w3) {
    int w = blockIdx.z;
    const float* src = (w == 0) ? w0 : (w == 1) ? w1 : (w == 2) ? w2 : w3;
    __shared__ float tile[32][33];
    int kb = blockIdx.x * 32, nb = blockIdx.y * 32;
    int tx = threadIdx.x & 31, ty = threadIdx.x >> 5;
    #pragma unroll
    for (int i = 0; i < 32; i += 8)
        tile[ty + i][tx] = src[(size_t)(kb + ty + i) * NHD + nb + tx];
    __syncthreads();
    __half* dh = g_wh[w];
    #pragma unroll
    for (int i = 0; i < 32; i += 8) {
        float v = tile[tx][ty + i];            // = W[kb+tx][nb+ty+i]
        int n = nb + ty + i, k = kb + tx;
        __half h = __float2half_rn(v);
        dh[(size_t)n * NE + k] = h;
        if (w == 3)
            g_wl[(size_t)n * NE + k] = __float2half_rn(v - __half2float(h));
    }
}

// ---------------------------------------------------------------------------
// fp16 GEMM: D = A @ B^T. A[M,K] K-major; B[N,K] K-major.
// 128x128 tile, BK=64, 8 warps (2x4), cp.async double buffer.
// CHAINS: 1 (B hi) or 2 (Bh + Bl error-split chains).
// MODE 0: WO — fp32 C = D + bias0 + resid.
// MODE 1: fused QKV (N=3072) — q *0.125; q,k,v fp16 stores.
// ---------------------------------------------------------------------------
template<int MODE, int CHAINS>
__global__ void __launch_bounds__(256) gemm_f16(
    const __half* __restrict__ A, const __half* __restrict__ Bh,
    const __half* __restrict__ Bl,
    const float* __restrict__ bias0, const float* __restrict__ bias1,
    const float* __restrict__ bias2, const float* __restrict__ resid,
    float* __restrict__ C)
{
    const unsigned STAGE = 16384u * (1 + CHAINS);
    extern __shared__ char smraw[];
    unsigned sa = (unsigned)__cvta_generic_to_shared(smraw);
    int tid = threadIdx.x;
    int bm = blockIdx.y, bn = blockIdx.x;
    int lane = tid & 31, wid = tid >> 5;
    int wm = wid >> 2, wn = wid & 3;

    float acc[4][4][4];
    #pragma unroll
    for (int i = 0; i < 4; i++)
        #pragma unroll
        for (int j = 0; j < 4; j++)
            #pragma unroll
            for (int c = 0; c < 4; c++) acc[i][j][c] = 0.f;

    auto issue = [&](int buf, int k0) {
        unsigned base = sa + buf * STAGE;
        #pragma unroll
        for (int i = 0; i < 4; i++) {
            int u = tid + i * 256;
            int row = u >> 3, c = u & 7;
            unsigned so = row * 128 + ((c ^ (row & 7)) << 4);
            cpa16(base + so,         A  + (size_t)(bm * 128 + row) * NE + k0 + c * 8);
            cpa16(base + 16384 + so, Bh + (size_t)(bn * 128 + row) * NE + k0 + c * 8);
            if (CHAINS == 2)
                cpa16(base + 32768 + so,
                      Bl + (size_t)(bn * 128 + row) * NE + k0 + c * 8);
        }
        cpa_commit();
    };

    const int iters = NE >> 6;      // K = 1024, BK = 64
    issue(0, 0);

    int r8 = lane & 7, sel = lane >> 3;
    for (int it = 0; it < iters; it++) {
        if (it + 1 < iters) {
            issue((it + 1) & 1, (it + 1) << 6);
            asm volatile("cp.async.wait_group 1;");
        } else {
            asm volatile("cp.async.wait_group 0;");
        }
        __syncthreads();

        unsigned ab  = sa + (it & 1) * STAGE;
        unsigned bbh = ab + 16384;
        unsigned bbl = ab + 32768;
        #pragma unroll
        for (int s = 0; s < 4; s++) {
            int ch = 2 * s + (sel >> 1);
            unsigned aH[4][4], bH[2][4], bL[2][4];
            #pragma unroll
            for (int mf = 0; mf < 4; mf++) {
                int row = wm * 64 + mf * 16 + r8 + ((sel & 1) << 3);
                ldsm4(aH[mf], ab + row * 128 + ((ch ^ (row & 7)) << 4));
            }
            #pragma unroll
            for (int np = 0; np < 2; np++) {
                int nrow = wn * 32 + np * 16 + r8 + ((sel & 1) << 3);
                unsigned so = nrow * 128 + ((ch ^ (nrow & 7)) << 4);
                ldsm4(bH[np], bbh + so);
                if (CHAINS == 2) ldsm4(bL[np], bbl + so);
            }
            #pragma unroll
            for (int mf = 0; mf < 4; mf++)
                #pragma unroll
                for (int nf = 0; nf < 4; nf++) {
                    mmaf16(acc[mf][nf], aH[mf],
                           bH[nf >> 1][nf & 1], bH[nf >> 1][(nf & 1) + 2]);
                    if (CHAINS == 2)
                        mmaf16(acc[mf][nf], aH[mf],
                               bL[nf >> 1][nf & 1], bL[nf >> 1][(nf & 1) + 2]);
                }
        }
        __syncthreads();
    }

    int g = lane >> 2, t2 = (lane & 3) * 2;
    if (MODE == 0) {
        #pragma unroll
        for (int mf = 0; mf < 4; mf++) {
            int row0 = bm * 128 + wm * 64 + mf * 16 + g;
            #pragma unroll
            for (int nf = 0; nf < 4; nf++) {
                int col = bn * 128 + wn * 32 + nf * 8 + t2;
                float b0 = bias0[col], b1 = bias0[col + 1];
                const float* rp0 = resid + (size_t)row0 * NHD + col;
                const float* rp1 = resid + (size_t)(row0 + 8) * NHD + col;
                *(float2*)(C + (size_t)row0 * NHD + col) =
                    make_float2(acc[mf][nf][0] + b0 + rp0[0],
                                acc[mf][nf][1] + b1 + rp0[1]);
                *(float2*)(C + (size_t)(row0 + 8) * NHD + col) =
                    make_float2(acc[mf][nf][2] + b0 + rp1[0],
                                acc[mf][nf][3] + b1 + rp1[1]);
            }
        }
    } else {
        int which = bn >> 3;                  // 0:q 1:k 2:v
        const float* bias = (which == 0) ? bias0 : (which == 1) ? bias1 : bias2;
        float scl = (which == 0) ? 0.125f : 1.0f;
        __half* Ch = (which == 0) ? g_qh : (which == 1) ? g_kh : g_vh;
        #pragma unroll
        for (int mf = 0; mf < 4; mf++) {
            int row0 = bm * 128 + wm * 64 + mf * 16 + g;
            #pragma unroll
            for (int nf = 0; nf < 4; nf++) {
                int col = (bn & 7) * 128 + wn * 32 + nf * 8 + t2;
                float v00 = (acc[mf][nf][0] + bias[col])     * scl;
                float v01 = (acc[mf][nf][1] + bias[col + 1]) * scl;
                float v10 = (acc[mf][nf][2] + bias[col])     * scl;
                float v11 = (acc[mf][nf][3] + bias[col + 1]) * scl;
                *(__half2*)(Ch + (size_t)row0 * NHD + col) =
                    __floats2half2_rn(v00, v01);
                *(__half2*)(Ch + (size_t)(row0 + 8) * NHD + col) =
                    __floats2half2_rn(v10, v11);
            }
        }
    }
}

// ---------------------------------------------------------------------------
// Pure-fp16 tensor-core causal flash attention.
// Block = 4 warps, 64 q-rows, per (b,h). Q/K/V hi only, KV double-buffered.
// Smem: Q 8K | 2 x (K 8K | V 8K) = 40KB.
// ---------------------------------------------------------------------------
__global__ void __launch_bounds__(128) attn_tc_kernel() {
    extern __shared__ char smraw[];
    unsigned sb = (unsigned)__cvta_generic_to_shared(smraw);
    int tid = threadIdx.x, lane = tid & 31, wid = tid >> 5;
    int qt = (int)gridDim.x - 1 - (int)blockIdx.x;   // long blocks first
    int h = blockIdx.y, b = blockIdx.z;
    int g = lane >> 2, t2 = (lane & 3) * 2;
    int r8 = lane & 7, sel = lane >> 3;

    size_t qrow0 = (size_t)(b * NS + qt * 64);

    // Stage Q (group 1)
    #pragma unroll
    for (int i = 0; i < 4; i++) {
        int u = tid + i * 128;
        int row = u >> 3, c = u & 7;
        size_t go = (qrow0 + row) * NHD + h * ND + c * 8;
        cpa16(sb + row * 128 + ((c ^ (row & 7)) << 4), g_qh + go);
    }
    cpa_commit();

    auto issueKV = [&](int buf, int kt) {
        unsigned base = sb + 8192 + buf * 16384;
        size_t krow0 = (size_t)(b * NS + kt * 64);
        #pragma unroll
        for (int i = 0; i < 4; i++) {
            int u = tid + i * 128;
            int row = u >> 3, c = u & 7;
            size_t go = (krow0 + row) * NHD + h * ND + c * 8;
            unsigned so = row * 128 + ((c ^ (row & 7)) << 4);
            cpa16(base + so,        g_kh + go);
            cpa16(base + 8192 + so, g_vh + go);
        }
        cpa_commit();
    };
    issueKV(0, 0);

    // Q fragments (A, m16k16), 4 k-chunks
    asm volatile("cp.async.wait_group 1;");
    __syncthreads();
    unsigned aQ[4][4];
    #pragma unroll
    for (int kc = 0; kc < 4; kc++) {
        int row = wid * 16 + r8 + ((sel & 1) << 3);
        int ch = 2 * kc + (sel >> 1);
        ldsm4(aQ[kc], sb + row * 128 + ((ch ^ (row & 7)) << 4));
    }

    float o[8][4];
    #pragma unroll
    for (int d = 0; d < 8; d++)
        #pragma unroll
        for (int c = 0; c < 4; c++) o[d][c] = 0.f;
    float m0 = -3e38f, m1 = -3e38f, l0 = 0.f, l1 = 0.f;

    for (int kt = 0; kt <= qt; kt++) {
        __syncthreads();
        if (kt < qt) {
            issueKV((kt + 1) & 1, kt + 1);
            asm volatile("cp.async.wait_group 1;");
        } else {
            asm volatile("cp.async.wait_group 0;");
        }
        __syncthreads();
        unsigned kb = sb + 8192 + (kt & 1) * 16384;

        // ---- S = Q K^T ----
        float s[8][4];
        #pragma unroll
        for (int jf = 0; jf < 8; jf++)
            #pragma unroll
            for (int c = 0; c < 4; c++) s[jf][c] = 0.f;

        #pragma unroll
        for (int kc = 0; kc < 4; kc++) {
            unsigned bh[4][4];
            #pragma unroll
            for (int jp = 0; jp < 4; jp++) {
                int jrow = jp * 16 + ((sel >> 1) << 3) + r8;
                int ch = 2 * kc + (sel & 1);
                ldsm4(bh[jp], kb + jrow * 128 + ((ch ^ (jrow & 7)) << 4));
            }
            #pragma unroll
            for (int jf = 0; jf < 8; jf++)
                mmaf16(s[jf], aQ[kc],
                       bh[jf >> 1][(jf & 1) * 2], bh[jf >> 1][(jf & 1) * 2 + 1]);
        }

        // ---- causal mask on diagonal tile ----
        if (kt == qt) {
            int rowg = wid * 16 + g;
            #pragma unroll
            for (int jf = 0; jf < 8; jf++) {
                int col = jf * 8 + t2;
                if (col     > rowg)     s[jf][0] = -1e30f;
                if (col + 1 > rowg)     s[jf][1] = -1e30f;
                if (col     > rowg + 8) s[jf][2] = -1e30f;
                if (col + 1 > rowg + 8) s[jf][3] = -1e30f;
            }
        }

        // ---- online softmax ----
        float mx0 = -1e30f, mx1 = -1e30f;
        #pragma unroll
        for (int jf = 0; jf < 8; jf++) {
            mx0 = fmaxf(mx0, fmaxf(s[jf][0], s[jf][1]));
            mx1 = fmaxf(mx1, fmaxf(s[jf][2], s[jf][3]));
        }
        mx0 = fmaxf(mx0, __shfl_xor_sync(0xffffffffu, mx0, 1));
        mx0 = fmaxf(mx0, __shfl_xor_sync(0xffffffffu, mx0, 2));
        mx1 = fmaxf(mx1, __shfl_xor_sync(0xffffffffu, mx1, 1));
        mx1 = fmaxf(mx1, __shfl_xor_sync(0xffffffffu, mx1, 2));
        float mn0 = fmaxf(m0, mx0), mn1 = fmaxf(m1, mx1);
        float a0 = __expf(m0 - mn0), a1 = __expf(m1 - mn1);
        m0 = mn0; m1 = mn1;

        unsigned ph[4][4];
        float ps0 = 0.f, ps1 = 0.f;
        #pragma unroll
        for (int jf = 0; jf < 8; jf++) {
            float p0 = __expf(s[jf][0] - mn0);
            float p1 = __expf(s[jf][1] - mn0);
            float p2 = __expf(s[jf][2] - mn1);
            float p3 = __expf(s[jf][3] - mn1);
            ps0 += p0 + p1; ps1 += p2 + p3;
            int kc = jf >> 1, hi = (jf & 1) * 2;
            ph[kc][hi]     = packh2(p0, p1);
            ph[kc][hi + 1] = packh2(p2, p3);
        }
        ps0 += __shfl_xor_sync(0xffffffffu, ps0, 1);
        ps0 += __shfl_xor_sync(0xffffffffu, ps0, 2);
        ps1 += __shfl_xor_sync(0xffffffffu, ps1, 1);
        ps1 += __shfl_xor_sync(0xffffffffu, ps1, 2);
        l0 = l0 * a0 + ps0;
        l1 = l1 * a1 + ps1;
        #pragma unroll
        for (int d = 0; d < 8; d++) {
            o[d][0] *= a0; o[d][1] *= a0;
            o[d][2] *= a1; o[d][3] *= a1;
        }

        // ---- O += P V ----
        #pragma unroll
        for (int kc = 0; kc < 4; kc++) {
            unsigned vh[4][4];
            #pragma unroll
            for (int np = 0; np < 4; np++) {
                int krow = kc * 16 + (lane & 15);
                int ch = np * 2 + (lane >> 4);
                ldsm4t(vh[np], kb + 8192 + krow * 128 + ((ch ^ (krow & 7)) << 4));
            }
            #pragma unroll
            for (int df = 0; df < 8; df++)
                mmaf16(o[df], ph[kc],
                       vh[df >> 1][(df & 1) * 2], vh[df >> 1][(df & 1) * 2 + 1]);
        }
    }

    // ---- epilogue: normalize, fp16 out ----
    float inv0 = 1.f / l0, inv1 = 1.f / l1;
    size_t row0 = qrow0 + wid * 16 + g;
    #pragma unroll
    for (int df = 0; df < 8; df++) {
        int col = h * ND + df * 8 + t2;
        *(__half2*)(g_aoh + row0 * NHD + col) =
            __floats2half2_rn(o[df][0] * inv0, o[df][1] * inv0);
        *(__half2*)(g_aoh + (row0 + 8) * NHD + col) =
            __floats2half2_rn(o[df][2] * inv1, o[df][3] * inv1);
    }
}

// ---------------------------------------------------------------------------
// Launch
// ---------------------------------------------------------------------------
extern "C" void kernel_launch(void* const* d_in, const int* in_sizes, int n_in,
                              void* d_out, int out_size) {
    const float* x    = (const float*)d_in[0];
    const float* ln_g = (const float*)d_in[1];
    const float* ln_b = (const float*)d_in[2];
    const float* wq   = (const float*)d_in[3];
    const float* bq   = (const float*)d_in[4];
    const float* wk   = (const float*)d_in[5];
    const float* bk   = (const float*)d_in[6];
    const float* wv   = (const float*)d_in[7];
    const float* bv   = (const float*)d_in[8];
    const float* wo   = (const float*)d_in[9];
    const float* bo   = (const float*)d_in[10];
    float* out = (float*)d_out;

    __half *xnh, *aoh, *wh, *wl;
    cudaGetSymbolAddress((void**)&xnh, g_xnh);
    cudaGetSymbolAddress((void**)&aoh, g_aoh);
    cudaGetSymbolAddress((void**)&wh,  g_wh);
    cudaGetSymbolAddress((void**)&wl,  g_wl);

    ln_kernel<<<NM, 256>>>(x, ln_g, ln_b);
    splitwT_kernel<<<dim3(32, 32, 4), 256>>>(wq, wk, wv, wo);

    cudaFuncSetAttribute(gemm_f16<1, 1>,
                         cudaFuncAttributeMaxDynamicSharedMemorySize, 65536);
    cudaFuncSetAttribute(gemm_f16<0, 2>,
                         cudaFuncAttributeMaxDynamicSharedMemorySize, 98304);

    const size_t WN = (size_t)NE * NHD;
    // fused QKV (single chain): B rows 0..3071 span g_wh[0..2]
    gemm_f16<1, 1><<<dim3(3 * NHD / 128, NM / 128), 256, 65536>>>(
        xnh, wh, nullptr, bq, bk, bv, nullptr, nullptr);

    cudaFuncSetAttribute(attn_tc_kernel,
                         cudaFuncAttributeMaxDynamicSharedMemorySize, 40960);
    attn_tc_kernel<<<dim3(NS / 64, NH, NB), 128, 40960>>>();

    // WO (2-chain for output accuracy)
    gemm_f16<0, 2><<<dim3(NE / 128, NM / 128), 256, 98304>>>(
        aoh, wh + 3 * WN, wl, bo, nullptr, nullptr, x, out);
}

// round 7
// speedup vs baseline: 7.0907x; 1.1416x over previous
#include <cuda_runtime.h>
#include <cuda_fp16.h>
#include <cstdint>

#define NB 2
#define NS 2048
#define NE 1024
#define NH 16
#define ND 64
#define NM (NB*NS)      // 4096 rows
#define NHD (NH*ND)     // 1024

// ---------------------------------------------------------------------------
// Scratch (__device__ globals; allocation-free rule)
// ---------------------------------------------------------------------------
__device__ __align__(16) __half g_xnh[NM*NE];          // LN out, fp16
__device__ __align__(16) __half g_qh[NM*NHD];          // q (pre-scaled)
__device__ __align__(16) __half g_kh[NM*NHD];
__device__ __align__(16) __half g_vh[NM*NHD];
__device__ __align__(16) __half g_aoh[NM*NHD];         // attention out
// weights TRANSPOSED: [N][K] K-major; [0..2] = q,k,v (contiguous), [3] = o
__device__ __align__(16) __half g_wh[4][NE*NHD];

// q pre-scale: (1/sqrt(64)) * log2(e)  — softmax runs in exp2 domain
#define QSCALE 0.1803368801111204f

// ---------------------------------------------------------------------------
// PTX helpers
// ---------------------------------------------------------------------------
__device__ __forceinline__ void ldsm4(unsigned r[4], unsigned addr) {
    asm volatile("ldmatrix.sync.aligned.m8n8.x4.shared.b16 {%0,%1,%2,%3}, [%4];"
                 : "=r"(r[0]), "=r"(r[1]), "=r"(r[2]), "=r"(r[3]) : "r"(addr));
}
__device__ __forceinline__ void ldsm4t(unsigned r[4], unsigned addr) {
    asm volatile("ldmatrix.sync.aligned.m8n8.x4.trans.shared.b16 {%0,%1,%2,%3}, [%4];"
                 : "=r"(r[0]), "=r"(r[1]), "=r"(r[2]), "=r"(r[3]) : "r"(addr));
}
__device__ __forceinline__ void mmaf16(float d[4], const unsigned a[4],
                                       unsigned b0, unsigned b1) {
    asm volatile("mma.sync.aligned.m16n8k16.row.col.f32.f16.f16.f32 "
                 "{%0,%1,%2,%3}, {%4,%5,%6,%7}, {%8,%9}, {%0,%1,%2,%3};"
                 : "+f"(d[0]), "+f"(d[1]), "+f"(d[2]), "+f"(d[3])
                 : "r"(a[0]), "r"(a[1]), "r"(a[2]), "r"(a[3]), "r"(b0), "r"(b1));
}
__device__ __forceinline__ void cpa16(unsigned saddr, const void* g) {
    asm volatile("cp.async.cg.shared.global [%0], [%1], 16;" :: "r"(saddr), "l"(g));
}
__device__ __forceinline__ void cpa_commit() {
    asm volatile("cp.async.commit_group;");
}
__device__ __forceinline__ unsigned packh2(float a, float b) {
    __half2 t = __floats2half2_rn(a, b);
    return *(unsigned*)&t;
}
__device__ __forceinline__ float ex2(float x) {
    float y;
    asm("ex2.approx.f32 %0, %1;" : "=f"(y) : "f"(x));
    return y;
}

// ---------------------------------------------------------------------------
// LayerNorm: one block per row; fp16 output
// ---------------------------------------------------------------------------
__global__ void __launch_bounds__(256) ln_kernel(const float* __restrict__ x,
                                                 const float* __restrict__ gam,
                                                 const float* __restrict__ bet) {
    int row = blockIdx.x;
    int t = threadIdx.x;
    const float4* xr = (const float4*)(x + (size_t)row * NE);
    float4 xv = xr[t];
    float s  = xv.x + xv.y + xv.z + xv.w;
    float ss = xv.x*xv.x + xv.y*xv.y + xv.z*xv.z + xv.w*xv.w;
    #pragma unroll
    for (int m = 16; m; m >>= 1) {
        s  += __shfl_xor_sync(0xffffffffu, s,  m);
        ss += __shfl_xor_sync(0xffffffffu, ss, m);
    }
    __shared__ float sh1[8], sh2[8];
    if ((t & 31) == 0) { sh1[t >> 5] = s; sh2[t >> 5] = ss; }
    __syncthreads();
    s = 0.f; ss = 0.f;
    #pragma unroll
    for (int w = 0; w < 8; w++) { s += sh1[w]; ss += sh2[w]; }
    float mean = s * (1.f / NE);
    float var  = ss * (1.f / NE) - mean * mean;
    float rstd = rsqrtf(var + 1e-5f);
    float4 gv = ((const float4*)gam)[t];
    float4 bv = ((const float4*)bet)[t];
    __half2 o0 = __floats2half2_rn((xv.x - mean) * rstd * gv.x + bv.x,
                                   (xv.y - mean) * rstd * gv.y + bv.y);
    __half2 o1 = __floats2half2_rn((xv.z - mean) * rstd * gv.z + bv.z,
                                   (xv.w - mean) * rstd * gv.w + bv.w);
    __half2* dst = (__half2*)(g_xnh + (size_t)row * NE + t * 4);
    dst[0] = o0; dst[1] = o1;
}

// ---------------------------------------------------------------------------
// Weight transpose + fp16 convert: W[K,N] fp32 -> Wt[N,K] fp16
// ---------------------------------------------------------------------------
__global__ void __launch_bounds__(256) splitwT_kernel(
    const float* __restrict__ w0, const float* __restrict__ w1,
    const float* __restrict__ w2, const float* __restrict__ w3) {
    int w = blockIdx.z;
    const float* src = (w == 0) ? w0 : (w == 1) ? w1 : (w == 2) ? w2 : w3;
    __shared__ float tile[32][33];
    int kb = blockIdx.x * 32, nb = blockIdx.y * 32;
    int tx = threadIdx.x & 31, ty = threadIdx.x >> 5;
    #pragma unroll
    for (int i = 0; i < 32; i += 8)
        tile[ty + i][tx] = src[(size_t)(kb + ty + i) * NHD + nb + tx];
    __syncthreads();
    __half* dh = g_wh[w];
    #pragma unroll
    for (int i = 0; i < 32; i += 8) {
        float v = tile[tx][ty + i];            // = W[kb+tx][nb+ty+i]
        int n = nb + ty + i, k = kb + tx;
        dh[(size_t)n * NE + k] = __float2half_rn(v);
    }
}

// ---------------------------------------------------------------------------
// fp16 GEMM: D = A @ B^T. A[M,K] K-major; B[N,K] K-major. Single chain.
// 128x128 tile, BK=64, 8 warps (2x4), cp.async double buffer (2x32KB).
// MODE 0: WO — fp32 C = D + bias0 + resid.
// MODE 1: fused QKV (N=3072) — q *QSCALE; q,k,v fp16 stores.
// ---------------------------------------------------------------------------
template<int MODE>
__global__ void __launch_bounds__(256) gemm_f16(
    const __half* __restrict__ A, const __half* __restrict__ Bh,
    const float* __restrict__ bias0, const float* __restrict__ bias1,
    const float* __restrict__ bias2, const float* __restrict__ resid,
    float* __restrict__ C)
{
    extern __shared__ char smraw[];
    unsigned sa = (unsigned)__cvta_generic_to_shared(smraw);
    int tid = threadIdx.x;
    int bm = blockIdx.y, bn = blockIdx.x;
    int lane = tid & 31, wid = tid >> 5;
    int wm = wid >> 2, wn = wid & 3;

    float acc[4][4][4];
    #pragma unroll
    for (int i = 0; i < 4; i++)
        #pragma unroll
        for (int j = 0; j < 4; j++)
            #pragma unroll
            for (int c = 0; c < 4; c++) acc[i][j][c] = 0.f;

    auto issue = [&](int buf, int k0) {
        unsigned base = sa + buf * 32768;
        #pragma unroll
        for (int i = 0; i < 4; i++) {
            int u = tid + i * 256;
            int row = u >> 3, c = u & 7;
            unsigned so = row * 128 + ((c ^ (row & 7)) << 4);
            cpa16(base + so,         A  + (size_t)(bm * 128 + row) * NE + k0 + c * 8);
            cpa16(base + 16384 + so, Bh + (size_t)(bn * 128 + row) * NE + k0 + c * 8);
        }
        cpa_commit();
    };

    const int iters = NE >> 6;      // K = 1024, BK = 64
    issue(0, 0);

    int r8 = lane & 7, sel = lane >> 3;
    for (int it = 0; it < iters; it++) {
        if (it + 1 < iters) {
            issue((it + 1) & 1, (it + 1) << 6);
            asm volatile("cp.async.wait_group 1;");
        } else {
            asm volatile("cp.async.wait_group 0;");
        }
        __syncthreads();

        unsigned ab  = sa + (it & 1) * 32768;
        unsigned bbh = ab + 16384;
        #pragma unroll
        for (int s = 0; s < 4; s++) {
            int ch = 2 * s + (sel >> 1);
            unsigned aH[4][4], bH[2][4];
            #pragma unroll
            for (int mf = 0; mf < 4; mf++) {
                int row = wm * 64 + mf * 16 + r8 + ((sel & 1) << 3);
                ldsm4(aH[mf], ab + row * 128 + ((ch ^ (row & 7)) << 4));
            }
            #pragma unroll
            for (int np = 0; np < 2; np++) {
                int nrow = wn * 32 + np * 16 + r8 + ((sel & 1) << 3);
                ldsm4(bH[np], bbh + nrow * 128 + ((ch ^ (nrow & 7)) << 4));
            }
            #pragma unroll
            for (int mf = 0; mf < 4; mf++)
                #pragma unroll
                for (int nf = 0; nf < 4; nf++)
                    mmaf16(acc[mf][nf], aH[mf],
                           bH[nf >> 1][nf & 1], bH[nf >> 1][(nf & 1) + 2]);
        }
        __syncthreads();
    }

    int g = lane >> 2, t2 = (lane & 3) * 2;
    if (MODE == 0) {
        #pragma unroll
        for (int mf = 0; mf < 4; mf++) {
            int row0 = bm * 128 + wm * 64 + mf * 16 + g;
            #pragma unroll
            for (int nf = 0; nf < 4; nf++) {
                int col = bn * 128 + wn * 32 + nf * 8 + t2;
                float b0 = bias0[col], b1 = bias0[col + 1];
                const float* rp0 = resid + (size_t)row0 * NHD + col;
                const float* rp1 = resid + (size_t)(row0 + 8) * NHD + col;
                *(float2*)(C + (size_t)row0 * NHD + col) =
                    make_float2(acc[mf][nf][0] + b0 + rp0[0],
                                acc[mf][nf][1] + b1 + rp0[1]);
                *(float2*)(C + (size_t)(row0 + 8) * NHD + col) =
                    make_float2(acc[mf][nf][2] + b0 + rp1[0],
                                acc[mf][nf][3] + b1 + rp1[1]);
            }
        }
    } else {
        int which = bn >> 3;                  // 0:q 1:k 2:v
        const float* bias = (which == 0) ? bias0 : (which == 1) ? bias1 : bias2;
        float scl = (which == 0) ? QSCALE : 1.0f;
        __half* Ch = (which == 0) ? g_qh : (which == 1) ? g_kh : g_vh;
        #pragma unroll
        for (int mf = 0; mf < 4; mf++) {
            int row0 = bm * 128 + wm * 64 + mf * 16 + g;
            #pragma unroll
            for (int nf = 0; nf < 4; nf++) {
                int col = (bn & 7) * 128 + wn * 32 + nf * 8 + t2;
                float v00 = (acc[mf][nf][0] + bias[col])     * scl;
                float v01 = (acc[mf][nf][1] + bias[col + 1]) * scl;
                float v10 = (acc[mf][nf][2] + bias[col])     * scl;
                float v11 = (acc[mf][nf][3] + bias[col + 1]) * scl;
                *(__half2*)(Ch + (size_t)row0 * NHD + col) =
                    __floats2half2_rn(v00, v01);
                *(__half2*)(Ch + (size_t)(row0 + 8) * NHD + col) =
                    __floats2half2_rn(v10, v11);
            }
        }
    }
}

// ---------------------------------------------------------------------------
// Pure-fp16 tensor-core causal flash attention, exp2-domain softmax.
// Block = 4 warps, 64 q-rows, per (b,h). 3-stage KV pipeline.
// Smem: Q 8K | 3 x (K 8K | V 8K) = 56KB.
// ---------------------------------------------------------------------------
__global__ void __launch_bounds__(128) attn_tc_kernel() {
    extern __shared__ char smraw[];
    unsigned sb = (unsigned)__cvta_generic_to_shared(smraw);
    int tid = threadIdx.x, lane = tid & 31, wid = tid >> 5;
    int qt = (int)gridDim.x - 1 - (int)blockIdx.x;   // long blocks first
    int h = blockIdx.y, b = blockIdx.z;
    int g = lane >> 2, t2 = (lane & 3) * 2;
    int r8 = lane & 7, sel = lane >> 3;

    size_t qrow0 = (size_t)(b * NS + qt * 64);

    // Stage Q (own commit group)
    #pragma unroll
    for (int i = 0; i < 4; i++) {
        int u = tid + i * 128;
        int row = u >> 3, c = u & 7;
        size_t go = (qrow0 + row) * NHD + h * ND + c * 8;
        cpa16(sb + row * 128 + ((c ^ (row & 7)) << 4), g_qh + go);
    }
    cpa_commit();

    auto issueKV = [&](int buf, int kt) {
        unsigned base = sb + 8192 + buf * 16384;
        size_t krow0 = (size_t)(b * NS + kt * 64);
        #pragma unroll
        for (int i = 0; i < 4; i++) {
            int u = tid + i * 128;
            int row = u >> 3, c = u & 7;
            size_t go = (krow0 + row) * NHD + h * ND + c * 8;
            unsigned so = row * 128 + ((c ^ (row & 7)) << 4);
            cpa16(base + so,        g_kh + go);
            cpa16(base + 8192 + so, g_vh + go);
        }
        cpa_commit();
    };
    issueKV(0, 0);
    if (qt >= 1) issueKV(1, 1);

    // Wait for Q group (KV groups may stay pending), then load Q fragments
    if (qt >= 1) asm volatile("cp.async.wait_group 2;");
    else         asm volatile("cp.async.wait_group 1;");
    __syncthreads();
    unsigned aQ[4][4];
    #pragma unroll
    for (int kc = 0; kc < 4; kc++) {
        int row = wid * 16 + r8 + ((sel & 1) << 3);
        int ch = 2 * kc + (sel >> 1);
        ldsm4(aQ[kc], sb + row * 128 + ((ch ^ (row & 7)) << 4));
    }

    float o[8][4];
    #pragma unroll
    for (int d = 0; d < 8; d++)
        #pragma unroll
        for (int c = 0; c < 4; c++) o[d][c] = 0.f;
    float m0 = -3e38f, m1 = -3e38f, l0 = 0.f, l1 = 0.f;

    int buf = 0;
    for (int kt = 0; kt <= qt; kt++) {
        __syncthreads();      // all warps done reading the buffer being refilled
        if (kt + 2 <= qt) {
            int nb2 = buf + 2; if (nb2 >= 3) nb2 -= 3;
            issueKV(nb2, kt + 2);
        }
        int rem = qt - kt;
        if (rem >= 2)      asm volatile("cp.async.wait_group 2;");
        else if (rem == 1) asm volatile("cp.async.wait_group 1;");
        else               asm volatile("cp.async.wait_group 0;");
        __syncthreads();
        unsigned kb = sb + 8192 + buf * 16384;

        // ---- S = Q K^T (exp2 domain: q pre-scaled by 1/8*log2e) ----
        float s[8][4];
        #pragma unroll
        for (int jf = 0; jf < 8; jf++)
            #pragma unroll
            for (int c = 0; c < 4; c++) s[jf][c] = 0.f;

        #pragma unroll
        for (int kc = 0; kc < 4; kc++) {
            unsigned bh[4][4];
            #pragma unroll
            for (int jp = 0; jp < 4; jp++) {
                int jrow = jp * 16 + ((sel >> 1) << 3) + r8;
                int ch = 2 * kc + (sel & 1);
                ldsm4(bh[jp], kb + jrow * 128 + ((ch ^ (jrow & 7)) << 4));
            }
            #pragma unroll
            for (int jf = 0; jf < 8; jf++)
                mmaf16(s[jf], aQ[kc],
                       bh[jf >> 1][(jf & 1) * 2], bh[jf >> 1][(jf & 1) * 2 + 1]);
        }

        // ---- causal mask on diagonal tile ----
        if (kt == qt) {
            int rowg = wid * 16 + g;
            #pragma unroll
            for (int jf = 0; jf < 8; jf++) {
                int col = jf * 8 + t2;
                if (col     > rowg)     s[jf][0] = -1e30f;
                if (col + 1 > rowg)     s[jf][1] = -1e30f;
                if (col     > rowg + 8) s[jf][2] = -1e30f;
                if (col + 1 > rowg + 8) s[jf][3] = -1e30f;
            }
        }

        // ---- online softmax (exp2) ----
        float mx0 = -1e30f, mx1 = -1e30f;
        #pragma unroll
        for (int jf = 0; jf < 8; jf++) {
            mx0 = fmaxf(mx0, fmaxf(s[jf][0], s[jf][1]));
            mx1 = fmaxf(mx1, fmaxf(s[jf][2], s[jf][3]));
        }
        mx0 = fmaxf(mx0, __shfl_xor_sync(0xffffffffu, mx0, 1));
        mx0 = fmaxf(mx0, __shfl_xor_sync(0xffffffffu, mx0, 2));
        mx1 = fmaxf(mx1, __shfl_xor_sync(0xffffffffu, mx1, 1));
        mx1 = fmaxf(mx1, __shfl_xor_sync(0xffffffffu, mx1, 2));
        float mn0 = fmaxf(m0, mx0), mn1 = fmaxf(m1, mx1);
        float a0 = ex2(m0 - mn0), a1 = ex2(m1 - mn1);
        m0 = mn0; m1 = mn1;

        unsigned ph[4][4];
        float ps0 = 0.f, ps1 = 0.f;
        #pragma unroll
        for (int jf = 0; jf < 8; jf++) {
            float p0 = ex2(s[jf][0] - mn0);
            float p1 = ex2(s[jf][1] - mn0);
            float p2 = ex2(s[jf][2] - mn1);
            float p3 = ex2(s[jf][3] - mn1);
            ps0 += p0 + p1; ps1 += p2 + p3;
            int kc = jf >> 1, hi = (jf & 1) * 2;
            ph[kc][hi]     = packh2(p0, p1);
            ph[kc][hi + 1] = packh2(p2, p3);
        }
        ps0 += __shfl_xor_sync(0xffffffffu, ps0, 1);
        ps0 += __shfl_xor_sync(0xffffffffu, ps0, 2);
        ps1 += __shfl_xor_sync(0xffffffffu, ps1, 1);
        ps1 += __shfl_xor_sync(0xffffffffu, ps1, 2);
        l0 = l0 * a0 + ps0;
        l1 = l1 * a1 + ps1;
        #pragma unroll
        for (int d = 0; d < 8; d++) {
            o[d][0] *= a0; o[d][1] *= a0;
            o[d][2] *= a1; o[d][3] *= a1;
        }

        // ---- O += P V ----
        #pragma unroll
        for (int kc = 0; kc < 4; kc++) {
            unsigned vh[4][4];
            #pragma unroll
            for (int np = 0; np < 4; np++) {
                int krow = kc * 16 + (lane & 15);
                int ch = np * 2 + (lane >> 4);
                ldsm4t(vh[np], kb + 8192 + krow * 128 + ((ch ^ (krow & 7)) << 4));
            }
            #pragma unroll
            for (int df = 0; df < 8; df++)
                mmaf16(o[df], ph[kc],
                       vh[df >> 1][(df & 1) * 2], vh[df >> 1][(df & 1) * 2 + 1]);
        }

        if (++buf >= 3) buf = 0;
    }

    // ---- epilogue: normalize, fp16 out ----
    float inv0 = 1.f / l0, inv1 = 1.f / l1;
    size_t row0 = qrow0 + wid * 16 + g;
    #pragma unroll
    for (int df = 0; df < 8; df++) {
        int col = h * ND + df * 8 + t2;
        *(__half2*)(g_aoh + row0 * NHD + col) =
            __floats2half2_rn(o[df][0] * inv0, o[df][1] * inv0);
        *(__half2*)(g_aoh + (row0 + 8) * NHD + col) =
            __floats2half2_rn(o[df][2] * inv1, o[df][3] * inv1);
    }
}

// ---------------------------------------------------------------------------
// Launch
// ---------------------------------------------------------------------------
extern "C" void kernel_launch(void* const* d_in, const int* in_sizes, int n_in,
                              void* d_out, int out_size) {
    const float* x    = (const float*)d_in[0];
    const float* ln_g = (const float*)d_in[1];
    const float* ln_b = (const float*)d_in[2];
    const float* wq   = (const float*)d_in[3];
    const float* bq   = (const float*)d_in[4];
    const float* wk   = (const float*)d_in[5];
    const float* bk   = (const float*)d_in[6];
    const float* wv   = (const float*)d_in[7];
    const float* bv   = (const float*)d_in[8];
    const float* wo   = (const float*)d_in[9];
    const float* bo   = (const float*)d_in[10];
    float* out = (float*)d_out;

    __half *xnh, *aoh, *wh;
    cudaGetSymbolAddress((void**)&xnh, g_xnh);
    cudaGetSymbolAddress((void**)&aoh, g_aoh);
    cudaGetSymbolAddress((void**)&wh,  g_wh);

    ln_kernel<<<NM, 256>>>(x, ln_g, ln_b);
    splitwT_kernel<<<dim3(32, 32, 4), 256>>>(wq, wk, wv, wo);

    cudaFuncSetAttribute(gemm_f16<1>,
                         cudaFuncAttributeMaxDynamicSharedMemorySize, 65536);
    cudaFuncSetAttribute(gemm_f16<0>,
                         cudaFuncAttributeMaxDynamicSharedMemorySize, 65536);

    const size_t WN = (size_t)NE * NHD;
    // fused QKV: B rows 0..3071 span g_wh[0..2]
    gemm_f16<1><<<dim3(3 * NHD / 128, NM / 128), 256, 65536>>>(
        xnh, wh, bq, bk, bv, nullptr, nullptr);

    cudaFuncSetAttribute(attn_tc_kernel,
                         cudaFuncAttributeMaxDynamicSharedMemorySize, 57344);
    attn_tc_kernel<<<dim3(NS / 64, NH, NB), 128, 57344>>>();

    gemm_f16<0><<<dim3(NE / 128, NM / 128), 256, 65536>>>(
        aoh, wh + 3 * WN, bo, nullptr, nullptr, x, out);
}

// round 8
// speedup vs baseline: 7.3564x; 1.0375x over previous
#include <cuda_runtime.h>
#include <cuda_fp16.h>
#include <cstdint>

#define NB 2
#define NS 2048
#define NE 1024
#define NH 16
#define ND 64
#define NM (NB*NS)      // 4096 rows
#define NHD (NH*ND)     // 1024

// ---------------------------------------------------------------------------
// Scratch (__device__ globals; allocation-free rule)
// ---------------------------------------------------------------------------
__device__ __align__(16) __half g_xnh[NM*NE];          // LN out, fp16
__device__ __align__(16) __half g_qh[NM*NHD];          // q (pre-scaled)
__device__ __align__(16) __half g_kh[NM*NHD];
__device__ __align__(16) __half g_vh[NM*NHD];
__device__ __align__(16) __half g_aoh[NM*NHD];         // attention out
// weights TRANSPOSED: [N][K] K-major; [0..2] = q,k,v (contiguous), [3] = o
__device__ __align__(16) __half g_wh[4][NE*NHD];

// q pre-scale: (1/sqrt(64)) * log2(e)  — softmax runs in exp2 domain
#define QSCALE 0.1803368801111204f

// ---------------------------------------------------------------------------
// PTX helpers
// ---------------------------------------------------------------------------
__device__ __forceinline__ void ldsm4(unsigned r[4], unsigned addr) {
    asm volatile("ldmatrix.sync.aligned.m8n8.x4.shared.b16 {%0,%1,%2,%3}, [%4];"
                 : "=r"(r[0]), "=r"(r[1]), "=r"(r[2]), "=r"(r[3]) : "r"(addr));
}
__device__ __forceinline__ void ldsm4t(unsigned r[4], unsigned addr) {
    asm volatile("ldmatrix.sync.aligned.m8n8.x4.trans.shared.b16 {%0,%1,%2,%3}, [%4];"
                 : "=r"(r[0]), "=r"(r[1]), "=r"(r[2]), "=r"(r[3]) : "r"(addr));
}
__device__ __forceinline__ void mmaf16(float d[4], const unsigned a[4],
                                       unsigned b0, unsigned b1) {
    asm volatile("mma.sync.aligned.m16n8k16.row.col.f32.f16.f16.f32 "
                 "{%0,%1,%2,%3}, {%4,%5,%6,%7}, {%8,%9}, {%0,%1,%2,%3};"
                 : "+f"(d[0]), "+f"(d[1]), "+f"(d[2]), "+f"(d[3])
                 : "r"(a[0]), "r"(a[1]), "r"(a[2]), "r"(a[3]), "r"(b0), "r"(b1));
}
__device__ __forceinline__ void cpa16(unsigned saddr, const void* g) {
    asm volatile("cp.async.cg.shared.global [%0], [%1], 16;" :: "r"(saddr), "l"(g));
}
__device__ __forceinline__ void cpa_commit() {
    asm volatile("cp.async.commit_group;");
}
__device__ __forceinline__ unsigned packh2(float a, float b) {
    __half2 t = __floats2half2_rn(a, b);
    return *(unsigned*)&t;
}
__device__ __forceinline__ float ex2(float x) {
    float y;
    asm("ex2.approx.f32 %0, %1;" : "=f"(y) : "f"(x));
    return y;
}
__device__ __forceinline__ unsigned ex2h2(unsigned x) {
    unsigned y;
    asm("ex2.approx.f16x2 %0, %1;" : "=r"(y) : "r"(x));
    return y;
}
__device__ __forceinline__ unsigned hadd2u(unsigned a, unsigned b) {
    __half2 r = __hadd2(*(__half2*)&a, *(__half2*)&b);
    return *(unsigned*)&r;
}

// ---------------------------------------------------------------------------
// LayerNorm: one block per row; fp16 output
// ---------------------------------------------------------------------------
__global__ void __launch_bounds__(256) ln_kernel(const float* __restrict__ x,
                                                 const float* __restrict__ gam,
                                                 const float* __restrict__ bet) {
    int row = blockIdx.x;
    int t = threadIdx.x;
    const float4* xr = (const float4*)(x + (size_t)row * NE);
    float4 xv = xr[t];
    float s  = xv.x + xv.y + xv.z + xv.w;
    float ss = xv.x*xv.x + xv.y*xv.y + xv.z*xv.z + xv.w*xv.w;
    #pragma unroll
    for (int m = 16; m; m >>= 1) {
        s  += __shfl_xor_sync(0xffffffffu, s,  m);
        ss += __shfl_xor_sync(0xffffffffu, ss, m);
    }
    __shared__ float sh1[8], sh2[8];
    if ((t & 31) == 0) { sh1[t >> 5] = s; sh2[t >> 5] = ss; }
    __syncthreads();
    s = 0.f; ss = 0.f;
    #pragma unroll
    for (int w = 0; w < 8; w++) { s += sh1[w]; ss += sh2[w]; }
    float mean = s * (1.f / NE);
    float var  = ss * (1.f / NE) - mean * mean;
    float rstd = rsqrtf(var + 1e-5f);
    float4 gv = ((const float4*)gam)[t];
    float4 bv = ((const float4*)bet)[t];
    __half2 o0 = __floats2half2_rn((xv.x - mean) * rstd * gv.x + bv.x,
                                   (xv.y - mean) * rstd * gv.y + bv.y);
    __half2 o1 = __floats2half2_rn((xv.z - mean) * rstd * gv.z + bv.z,
                                   (xv.w - mean) * rstd * gv.w + bv.w);
    __half2* dst = (__half2*)(g_xnh + (size_t)row * NE + t * 4);
    dst[0] = o0; dst[1] = o1;
}

// ---------------------------------------------------------------------------
// Weight transpose + fp16 convert: W[K,N] fp32 -> Wt[N,K] fp16
// ---------------------------------------------------------------------------
__global__ void __launch_bounds__(256) splitwT_kernel(
    const float* __restrict__ w0, const float* __restrict__ w1,
    const float* __restrict__ w2, const float* __restrict__ w3) {
    int w = blockIdx.z;
    const float* src = (w == 0) ? w0 : (w == 1) ? w1 : (w == 2) ? w2 : w3;
    __shared__ float tile[32][33];
    int kb = blockIdx.x * 32, nb = blockIdx.y * 32;
    int tx = threadIdx.x & 31, ty = threadIdx.x >> 5;
    #pragma unroll
    for (int i = 0; i < 32; i += 8)
        tile[ty + i][tx] = src[(size_t)(kb + ty + i) * NHD + nb + tx];
    __syncthreads();
    __half* dh = g_wh[w];
    #pragma unroll
    for (int i = 0; i < 32; i += 8) {
        float v = tile[tx][ty + i];            // = W[kb+tx][nb+ty+i]
        int n = nb + ty + i, k = kb + tx;
        dh[(size_t)n * NE + k] = __float2half_rn(v);
    }
}

// ---------------------------------------------------------------------------
// fp16 GEMM: D = A @ B^T. A[M,K] K-major; B[N,K] K-major. Single chain.
// 128x128 tile, BK=64, 8 warps (2x4), cp.async double buffer (2x32KB).
// MODE 0: WO — fp32 C = D + bias0 + resid.
// MODE 1: fused QKV (N=3072) — q *QSCALE; q,k,v fp16 stores.
// ---------------------------------------------------------------------------
template<int MODE>
__global__ void __launch_bounds__(256) gemm_f16(
    const __half* __restrict__ A, const __half* __restrict__ Bh,
    const float* __restrict__ bias0, const float* __restrict__ bias1,
    const float* __restrict__ bias2, const float* __restrict__ resid,
    float* __restrict__ C)
{
    extern __shared__ char smraw[];
    unsigned sa = (unsigned)__cvta_generic_to_shared(smraw);
    int tid = threadIdx.x;
    int bm = blockIdx.y, bn = blockIdx.x;
    int lane = tid & 31, wid = tid >> 5;
    int wm = wid >> 2, wn = wid & 3;

    float acc[4][4][4];
    #pragma unroll
    for (int i = 0; i < 4; i++)
        #pragma unroll
        for (int j = 0; j < 4; j++)
            #pragma unroll
            for (int c = 0; c < 4; c++) acc[i][j][c] = 0.f;

    auto issue = [&](int buf, int k0) {
        unsigned base = sa + buf * 32768;
        #pragma unroll
        for (int i = 0; i < 4; i++) {
            int u = tid + i * 256;
            int row = u >> 3, c = u & 7;
            unsigned so = row * 128 + ((c ^ (row & 7)) << 4);
            cpa16(base + so,         A  + (size_t)(bm * 128 + row) * NE + k0 + c * 8);
            cpa16(base + 16384 + so, Bh + (size_t)(bn * 128 + row) * NE + k0 + c * 8);
        }
        cpa_commit();
    };

    const int iters = NE >> 6;      // K = 1024, BK = 64
    issue(0, 0);

    int r8 = lane & 7, sel = lane >> 3;
    for (int it = 0; it < iters; it++) {
        if (it + 1 < iters) {
            issue((it + 1) & 1, (it + 1) << 6);
            asm volatile("cp.async.wait_group 1;");
        } else {
            asm volatile("cp.async.wait_group 0;");
        }
        __syncthreads();

        unsigned ab  = sa + (it & 1) * 32768;
        unsigned bbh = ab + 16384;
        #pragma unroll
        for (int s = 0; s < 4; s++) {
            int ch = 2 * s + (sel >> 1);
            unsigned aH[4][4], bH[2][4];
            #pragma unroll
            for (int mf = 0; mf < 4; mf++) {
                int row = wm * 64 + mf * 16 + r8 + ((sel & 1) << 3);
                ldsm4(aH[mf], ab + row * 128 + ((ch ^ (row & 7)) << 4));
            }
            #pragma unroll
            for (int np = 0; np < 2; np++) {
                int nrow = wn * 32 + np * 16 + r8 + ((sel & 1) << 3);
                ldsm4(bH[np], bbh + nrow * 128 + ((ch ^ (nrow & 7)) << 4));
            }
            #pragma unroll
            for (int mf = 0; mf < 4; mf++)
                #pragma unroll
                for (int nf = 0; nf < 4; nf++)
                    mmaf16(acc[mf][nf], aH[mf],
                           bH[nf >> 1][nf & 1], bH[nf >> 1][(nf & 1) + 2]);
        }
        __syncthreads();
    }

    int g = lane >> 2, t2 = (lane & 3) * 2;
    if (MODE == 0) {
        #pragma unroll
        for (int mf = 0; mf < 4; mf++) {
            int row0 = bm * 128 + wm * 64 + mf * 16 + g;
            #pragma unroll
            for (int nf = 0; nf < 4; nf++) {
                int col = bn * 128 + wn * 32 + nf * 8 + t2;
                float b0 = bias0[col], b1 = bias0[col + 1];
                const float* rp0 = resid + (size_t)row0 * NHD + col;
                const float* rp1 = resid + (size_t)(row0 + 8) * NHD + col;
                *(float2*)(C + (size_t)row0 * NHD + col) =
                    make_float2(acc[mf][nf][0] + b0 + rp0[0],
                                acc[mf][nf][1] + b1 + rp0[1]);
                *(float2*)(C + (size_t)(row0 + 8) * NHD + col) =
                    make_float2(acc[mf][nf][2] + b0 + rp1[0],
                                acc[mf][nf][3] + b1 + rp1[1]);
            }
        }
    } else {
        int which = bn >> 3;                  // 0:q 1:k 2:v
        const float* bias = (which == 0) ? bias0 : (which == 1) ? bias1 : bias2;
        float scl = (which == 0) ? QSCALE : 1.0f;
        __half* Ch = (which == 0) ? g_qh : (which == 1) ? g_kh : g_vh;
        #pragma unroll
        for (int mf = 0; mf < 4; mf++) {
            int row0 = bm * 128 + wm * 64 + mf * 16 + g;
            #pragma unroll
            for (int nf = 0; nf < 4; nf++) {
                int col = (bn & 7) * 128 + wn * 32 + nf * 8 + t2;
                float v00 = (acc[mf][nf][0] + bias[col])     * scl;
                float v01 = (acc[mf][nf][1] + bias[col + 1]) * scl;
                float v10 = (acc[mf][nf][2] + bias[col])     * scl;
                float v11 = (acc[mf][nf][3] + bias[col + 1]) * scl;
                *(__half2*)(Ch + (size_t)row0 * NHD + col) =
                    __floats2half2_rn(v00, v01);
                *(__half2*)(Ch + (size_t)(row0 + 8) * NHD + col) =
                    __floats2half2_rn(v10, v11);
            }
        }
    }
}

// ---------------------------------------------------------------------------
// Pure-fp16 tensor-core causal flash attention, exp2 f16x2 softmax.
// Block = 4 warps, 64 q-rows, per (b,h). 2-stage KV pipeline.
// Smem: Q 8K | 2 x (K 8K | V 8K) = 40KB  -> 4 CTAs/SM.
// ---------------------------------------------------------------------------
__global__ void __launch_bounds__(128) attn_tc_kernel() {
    extern __shared__ char smraw[];
    unsigned sb = (unsigned)__cvta_generic_to_shared(smraw);
    int tid = threadIdx.x, lane = tid & 31, wid = tid >> 5;
    int qt = (int)gridDim.x - 1 - (int)blockIdx.x;   // long blocks first
    int h = blockIdx.y, b = blockIdx.z;
    int g = lane >> 2, t2 = (lane & 3) * 2;
    int r8 = lane & 7, sel = lane >> 3;

    size_t qrow0 = (size_t)(b * NS + qt * 64);

    // Stage Q (own commit group)
    #pragma unroll
    for (int i = 0; i < 4; i++) {
        int u = tid + i * 128;
        int row = u >> 3, c = u & 7;
        size_t go = (qrow0 + row) * NHD + h * ND + c * 8;
        cpa16(sb + row * 128 + ((c ^ (row & 7)) << 4), g_qh + go);
    }
    cpa_commit();

    auto issueKV = [&](int buf, int kt) {
        unsigned base = sb + 8192 + buf * 16384;
        size_t krow0 = (size_t)(b * NS + kt * 64);
        #pragma unroll
        for (int i = 0; i < 4; i++) {
            int u = tid + i * 128;
            int row = u >> 3, c = u & 7;
            size_t go = (krow0 + row) * NHD + h * ND + c * 8;
            unsigned so = row * 128 + ((c ^ (row & 7)) << 4);
            cpa16(base + so,        g_kh + go);
            cpa16(base + 8192 + so, g_vh + go);
        }
        cpa_commit();
    };
    issueKV(0, 0);

    // Wait for Q group (KV0 may stay pending), then load Q fragments
    asm volatile("cp.async.wait_group 1;");
    __syncthreads();
    unsigned aQ[4][4];
    #pragma unroll
    for (int kc = 0; kc < 4; kc++) {
        int row = wid * 16 + r8 + ((sel & 1) << 3);
        int ch = 2 * kc + (sel >> 1);
        ldsm4(aQ[kc], sb + row * 128 + ((ch ^ (row & 7)) << 4));
    }

    float o[8][4];
    #pragma unroll
    for (int d = 0; d < 8; d++)
        #pragma unroll
        for (int c = 0; c < 4; c++) o[d][c] = 0.f;
    float m0 = -3e38f, m1 = -3e38f, l0 = 0.f, l1 = 0.f;

    for (int kt = 0; kt <= qt; kt++) {
        __syncthreads();      // all warps done reading the buffer being refilled
        if (kt < qt) {
            issueKV((kt + 1) & 1, kt + 1);
            asm volatile("cp.async.wait_group 1;");
        } else {
            asm volatile("cp.async.wait_group 0;");
        }
        __syncthreads();
        unsigned kb = sb + 8192 + (kt & 1) * 16384;

        // ---- S = Q K^T (exp2 domain: q pre-scaled by 1/8*log2e) ----
        float s[8][4];
        #pragma unroll
        for (int jf = 0; jf < 8; jf++)
            #pragma unroll
            for (int c = 0; c < 4; c++) s[jf][c] = 0.f;

        #pragma unroll
        for (int kc = 0; kc < 4; kc++) {
            unsigned bh[4][4];
            #pragma unroll
            for (int jp = 0; jp < 4; jp++) {
                int jrow = jp * 16 + ((sel >> 1) << 3) + r8;
                int ch = 2 * kc + (sel & 1);
                ldsm4(bh[jp], kb + jrow * 128 + ((ch ^ (jrow & 7)) << 4));
            }
            #pragma unroll
            for (int jf = 0; jf < 8; jf++)
                mmaf16(s[jf], aQ[kc],
                       bh[jf >> 1][(jf & 1) * 2], bh[jf >> 1][(jf & 1) * 2 + 1]);
        }

        // ---- causal mask on diagonal tile ----
        if (kt == qt) {
            int rowg = wid * 16 + g;
            #pragma unroll
            for (int jf = 0; jf < 8; jf++) {
                int col = jf * 8 + t2;
                if (col     > rowg)     s[jf][0] = -1e30f;
                if (col + 1 > rowg)     s[jf][1] = -1e30f;
                if (col     > rowg + 8) s[jf][2] = -1e30f;
                if (col + 1 > rowg + 8) s[jf][3] = -1e30f;
            }
        }

        // ---- online softmax (exp2, fp16x2 exp + fp16 tree sum) ----
        float mx0 = -1e30f, mx1 = -1e30f;
        #pragma unroll
        for (int jf = 0; jf < 8; jf++) {
            mx0 = fmaxf(mx0, fmaxf(s[jf][0], s[jf][1]));
            mx1 = fmaxf(mx1, fmaxf(s[jf][2], s[jf][3]));
        }
        mx0 = fmaxf(mx0, __shfl_xor_sync(0xffffffffu, mx0, 1));
        mx0 = fmaxf(mx0, __shfl_xor_sync(0xffffffffu, mx0, 2));
        mx1 = fmaxf(mx1, __shfl_xor_sync(0xffffffffu, mx1, 1));
        mx1 = fmaxf(mx1, __shfl_xor_sync(0xffffffffu, mx1, 2));
        float mn0 = fmaxf(m0, mx0), mn1 = fmaxf(m1, mx1);
        float a0 = ex2(m0 - mn0), a1 = ex2(m1 - mn1);
        m0 = mn0; m1 = mn1;

        unsigned ph[4][4];
        unsigned P01[8], P23[8];
        #pragma unroll
        for (int jf = 0; jf < 8; jf++) {
            P01[jf] = ex2h2(packh2(s[jf][0] - mn0, s[jf][1] - mn0));
            P23[jf] = ex2h2(packh2(s[jf][2] - mn1, s[jf][3] - mn1));
            int kc = jf >> 1, hi = (jf & 1) * 2;
            ph[kc][hi]     = P01[jf];
            ph[kc][hi + 1] = P23[jf];
        }
        // fp16 tree sums (depth 3), widen to fp32
        unsigned s01 = hadd2u(hadd2u(hadd2u(P01[0], P01[1]), hadd2u(P01[2], P01[3])),
                              hadd2u(hadd2u(P01[4], P01[5]), hadd2u(P01[6], P01[7])));
        unsigned s23 = hadd2u(hadd2u(hadd2u(P23[0], P23[1]), hadd2u(P23[2], P23[3])),
                              hadd2u(hadd2u(P23[4], P23[5]), hadd2u(P23[6], P23[7])));
        float2 f01 = __half22float2(*(__half2*)&s01);
        float2 f23 = __half22float2(*(__half2*)&s23);
        float ps0 = f01.x + f01.y;
        float ps1 = f23.x + f23.y;
        ps0 += __shfl_xor_sync(0xffffffffu, ps0, 1);
        ps0 += __shfl_xor_sync(0xffffffffu, ps0, 2);
        ps1 += __shfl_xor_sync(0xffffffffu, ps1, 1);
        ps1 += __shfl_xor_sync(0xffffffffu, ps1, 2);
        l0 = l0 * a0 + ps0;
        l1 = l1 * a1 + ps1;
        #pragma unroll
        for (int d = 0; d < 8; d++) {
            o[d][0] *= a0; o[d][1] *= a0;
            o[d][2] *= a1; o[d][3] *= a1;
        }

        // ---- O += P V ----
        #pragma unroll
        for (int kc = 0; kc < 4; kc++) {
            unsigned vh[4][4];
            #pragma unroll
            for (int np = 0; np < 4; np++) {
                int krow = kc * 16 + (lane & 15);
                int ch = np * 2 + (lane >> 4);
                ldsm4t(vh[np], kb + 8192 + krow * 128 + ((ch ^ (krow & 7)) << 4));
            }
            #pragma unroll
            for (int df = 0; df < 8; df++)
                mmaf16(o[df], ph[kc],
                       vh[df >> 1][(df & 1) * 2], vh[df >> 1][(df & 1) * 2 + 1]);
        }
    }

    // ---- epilogue: normalize, fp16 out ----
    float inv0 = 1.f / l0, inv1 = 1.f / l1;
    size_t row0 = qrow0 + wid * 16 + g;
    #pragma unroll
    for (int df = 0; df < 8; df++) {
        int col = h * ND + df * 8 + t2;
        *(__half2*)(g_aoh + row0 * NHD + col) =
            __floats2half2_rn(o[df][0] * inv0, o[df][1] * inv0);
        *(__half2*)(g_aoh + (row0 + 8) * NHD + col) =
            __floats2half2_rn(o[df][2] * inv1, o[df][3] * inv1);
    }
}

// ---------------------------------------------------------------------------
// Launch
// ---------------------------------------------------------------------------
extern "C" void kernel_launch(void* const* d_in, const int* in_sizes, int n_in,
                              void* d_out, int out_size) {
    const float* x    = (const float*)d_in[0];
    const float* ln_g = (const float*)d_in[1];
    const float* ln_b = (const float*)d_in[2];
    const float* wq   = (const float*)d_in[3];
    const float* bq   = (const float*)d_in[4];
    const float* wk   = (const float*)d_in[5];
    const float* bk   = (const float*)d_in[6];
    const float* wv   = (const float*)d_in[7];
    const float* bv   = (const float*)d_in[8];
    const float* wo   = (const float*)d_in[9];
    const float* bo   = (const float*)d_in[10];
    float* out = (float*)d_out;

    __half *xnh, *aoh, *wh;
    cudaGetSymbolAddress((void**)&xnh, g_xnh);
    cudaGetSymbolAddress((void**)&aoh, g_aoh);
    cudaGetSymbolAddress((void**)&wh,  g_wh);

    ln_kernel<<<NM, 256>>>(x, ln_g, ln_b);
    splitwT_kernel<<<dim3(32, 32, 4), 256>>>(wq, wk, wv, wo);

    cudaFuncSetAttribute(gemm_f16<1>,
                         cudaFuncAttributeMaxDynamicSharedMemorySize, 65536);
    cudaFuncSetAttribute(gemm_f16<0>,
                         cudaFuncAttributeMaxDynamicSharedMemorySize, 65536);

    const size_t WN = (size_t)NE * NHD;
    // fused QKV: B rows 0..3071 span g_wh[0..2]
    gemm_f16<1><<<dim3(3 * NHD / 128, NM / 128), 256, 65536>>>(
        xnh, wh, bq, bk, bv, nullptr, nullptr);

    cudaFuncSetAttribute(attn_tc_kernel,
                         cudaFuncAttributeMaxDynamicSharedMemorySize, 40960);
    attn_tc_kernel<<<dim3(NS / 64, NH, NB), 128, 40960>>>();

    gemm_f16<0><<<dim3(NE / 128, NM / 128), 256, 65536>>>(
        aoh, wh + 3 * WN, bo, nullptr, nullptr, x, out);
}